// round 12
// baseline (speedup 1.0000x reference)
#include <cuda_runtime.h>
#include <math.h>
#include <stdint.h>

// Problem constants
#define Tt   512
#define Bb   64
#define Dd   256
#define Uu   512
#define Mm   64
#define NZt  2112   // 4*U + M

#define NUBLK 128   // u-blocks: 4 u-cols each (16 z-cols)
#define NEBLK 8     // e-blocks: 8 e-cols each
#define NBLK  136
#define NTHR  544   // 512 main threads + 1 gate warp
#define NTILES (33 * 512)

// ---------------- device scratch (free-running across graph replays) ----------------
__device__ float g_Z[(size_t)Tt * NZt * Bb];   // Z[t][n][b]
__device__ float g_hTT[2][Uu][Bb];             // hidden state TRANSPOSED [u][b], double buffered
__device__ float g_ze[Bb][Mm];                 // pre-softmax e logits
__device__ float g_eprob[Bb][Mm];              // softmax probabilities (computed by e-blocks)

struct __align__(128) Cnt { unsigned int v; unsigned int pad[31]; };
__device__ Cnt g_hcnt;        // h arrivals   (128/step)
__device__ Cnt g_ecnt1;       // ze arrivals  (8/step)
__device__ Cnt g_ecnt2;       // eprob arrivals (8/step)
__device__ Cnt g_zdone;       // Z-phase barrier (+136 per replay)
__device__ Cnt g_tix;         // replay ticket counter (+136 per replay)
__device__ Cnt g_hmail[34];   // h epoch mailboxes (4 blocks/line)
__device__ Cnt g_zmail[8];    // ze epoch mailboxes (1 e-block/line)
__device__ Cnt g_pmail[32];   // eprob epoch mailboxes (4 u-blocks/line)

// SMEM float offsets
#define OFF_UD   0            // U duplicated [512 k][32] = 16384
#define OFF_CR   16384        // cring [64 slot][4 u][64 b] = 16384
#define OFF_HT   32768        // hT [512 k][36] = 18432  (ps2 aliases)
#define OFF_ZT   51200        // zt [16 c][65] = 1040
#define OFF_ZES  52240        // probs [64 b][65] = 4160
#define OFF_HST  56400        // h staging [4 uul][64 b] = 256
#define OFF_PSB  56656        // phase2 partial buffer [256]
#define OFF_GF   56912        // flags: 0=h ready t, 1=eprob ready t+1, 2=ze ready t+1
#define SMEM_F   56928        // 227712 bytes
// Z-phase scratch (overlaps UD/CR region, used strictly before them)
#define OFF_XS0  0
#define OFF_WS0  4160
#define OFF_XS1  8256
#define OFF_WS1  12416

// ---------------- PTX helpers ----------------
__device__ __forceinline__ void cp16(uint32_t dst, const float* src) {
    asm volatile("cp.async.cg.shared.global [%0], [%1], 16;" :: "r"(dst), "l"(src));
}
__device__ __forceinline__ void cp_commit() { asm volatile("cp.async.commit_group;"); }
__device__ __forceinline__ void cp_wait0()  { asm volatile("cp.async.wait_group 0;"); }
__device__ __forceinline__ unsigned ld_acq(const unsigned int* p) {
    unsigned v;
    asm volatile("ld.acquire.gpu.global.u32 %0, [%1];" : "=r"(v) : "l"(p));
    return v;
}
__device__ __forceinline__ unsigned atom_add_rel(unsigned int* p) {
    unsigned old;
    asm volatile("atom.add.release.gpu.global.u32 %0, [%1], 1;" : "=r"(old) : "l"(p) : "memory");
    return old;
}
__device__ __forceinline__ void st_rel_g(unsigned int* p, unsigned v) {
    asm volatile("st.release.gpu.global.u32 [%0], %1;" :: "l"(p), "r"(v));
}
__device__ __forceinline__ unsigned ld_acq_sh(const unsigned int* p) {
    unsigned v, a = (unsigned)__cvta_generic_to_shared(p);
    asm volatile("ld.acquire.cta.shared.u32 %0, [%1];" : "=r"(v) : "r"(a));
    return v;
}
__device__ __forceinline__ void st_rel_sh(unsigned int* p, unsigned v) {
    unsigned a = (unsigned)__cvta_generic_to_shared(p);
    asm volatile("st.release.cta.shared.u32 [%0], %1;" :: "r"(a), "r"(v));
}
#define MEMBAR_GL() asm volatile("membar.gl;" ::: "memory")
#define NBAR() asm volatile("bar.sync 1, 512;" ::: "memory")
#define TBAR(id) asm volatile("bar.sync %0, 256;" :: "r"(id) : "memory")

// packed fp32x2 FMA (FFMA2)
__device__ __forceinline__ unsigned long long pack2(float a, float b) {
    unsigned long long r;
    asm("mov.b64 %0, {%1, %2};" : "=l"(r) : "f"(a), "f"(b));
    return r;
}
__device__ __forceinline__ void fma2(unsigned long long& d,
                                     unsigned long long a, unsigned long long b) {
    asm("fma.rn.f32x2 %0, %1, %2, %0;" : "+l"(d) : "l"(a), "l"(b));
}
__device__ __forceinline__ void unpack2(unsigned long long v, float& a, float& b) {
    asm("mov.b64 {%0, %1}, %2;" : "=f"(a), "=f"(b) : "l"(v));
}

// ================= single fused kernel =================
__global__ __launch_bounds__(NTHR, 1) void xlstm_kernel(
    float* __restrict__ out, const float* __restrict__ x,
    const float* __restrict__ Wi, const float* __restrict__ Wf,
    const float* __restrict__ Wo, const float* __restrict__ Wc,
    const float* __restrict__ We,
    const float* __restrict__ bi, const float* __restrict__ bf,
    const float* __restrict__ bo, const float* __restrict__ bc,
    const float* __restrict__ be,
    const float* __restrict__ Ui, const float* __restrict__ Uf,
    const float* __restrict__ Uo, const float* __restrict__ Uc,
    const float* __restrict__ Ue)
{
    extern __shared__ float sm[];
    float* Ud  = sm + OFF_UD;
    float* cr  = sm + OFF_CR;
    float* hT  = sm + OFF_HT;
    float* ps2 = sm + OFF_HT;          // alias
    float* zt  = sm + OFF_ZT;
    float* zes = sm + OFF_ZES;
    float* hst = sm + OFF_HST;
    float* psb = sm + OFF_PSB;
    unsigned int* gf = (unsigned int*)(sm + OFF_GF);
    __shared__ unsigned sR;

    const uint32_t smem_u = (uint32_t)__cvta_generic_to_shared(sm);
    const int bid = blockIdx.x;
    const int tid = threadIdx.x;
    const bool isE = (bid >= NUBLK);

    if (tid == 0) {
        unsigned old = atomicAdd(&g_tix.v, 1u);
        sR = old / (unsigned)NBLK;
    }
    if (tid < 16) gf[tid] = 0u;
    __syncthreads();
    const unsigned R = sR;
    const unsigned EPB = R * 1024u;       // epoch base (mailbox values)
    const unsigned HB  = R * 65536u;      // h counter base (128*512)
    const unsigned EB  = R * 4096u;       // e counter base (8*512)

    // ======== gate warp (tids 512..543) ========
    if (tid >= 512) {
        const int lane = tid - 512;
        if (lane == 0) {
            const unsigned int* mp = &g_hmail[bid >> 2].v;
            for (int s = 1; s < Tt; s++) {
                while (ld_acq(mp) < EPB + (unsigned)s) { }
                st_rel_sh(&gf[0], (unsigned)s);
            }
        } else if (lane == 1 && !isE) {
            const unsigned int* mp = &g_pmail[bid >> 2].v;
            for (int t = 0; t < Tt; t++) {
                while (ld_acq(mp) < EPB + (unsigned)(t + 1)) { }
                st_rel_sh(&gf[1], (unsigned)(t + 1));
            }
        } else if (lane == 1 && isE) {
            const unsigned int* mp = &g_zmail[bid - NUBLK].v;
            for (int t = 0; t < Tt; t++) {
                while (ld_acq(mp) < EPB + (unsigned)(t + 1)) { }
                st_rel_sh(&gf[2], (unsigned)(t + 1));
            }
        }
        return;
    }

    // ================= PHASE A: precompute Z =================
    {
        const int team = tid >> 8;
        const int ttid = tid & 255;
        float* xs = sm + (team ? OFF_XS1 : OFF_XS0);
        float* Ws = sm + (team ? OFF_WS1 : OFF_WS0);
        const int barid = 2 + team;
        const int ptx = ttid & 15, pty = ttid >> 4;

        for (int tile = bid * 2 + team; tile < NTILES; tile += NBLK * 2) {
            const int t  = tile / 33;
            const int nt = tile % 33;
            const float* W; const float* bv;
            switch (nt >> 3) {
                case 0:  W = Wi; bv = bi; break;
                case 1:  W = Wf; bv = bf; break;
                case 2:  W = Wo; bv = bo; break;
                case 3:  W = Wc; bv = bc; break;
                default: W = We; bv = be; break;
            }
            const int stride = (nt < 32) ? Uu : Mm;
            const int col0   = (nt & 7) * 64;

            unsigned long long acc01[4], acc23[4];
            {
                unsigned long long p01 = pack2(bv[col0 + ptx * 4 + 0], bv[col0 + ptx * 4 + 1]);
                unsigned long long p23 = pack2(bv[col0 + ptx * 4 + 2], bv[col0 + ptx * 4 + 3]);
                #pragma unroll
                for (int i = 0; i < 4; i++) { acc01[i] = p01; acc23[i] = p23; }
            }
            for (int kb = 0; kb < 4; kb++) {
                TBAR(barid);
                #pragma unroll
                for (int l = 0; l < 16; l++) {
                    int idx = l * 256 + ttid;
                    int b = idx >> 6, kk = idx & 63;
                    xs[b * 65 + kk] = x[(size_t)b * Tt * Dd + (size_t)t * Dd + kb * 64 + kk];
                }
                #pragma unroll
                for (int l = 0; l < 16; l++) {
                    int idx = l * 256 + ttid;
                    int kk = idx >> 6, nn = idx & 63;
                    Ws[kk * 64 + nn] = W[(size_t)(kb * 64 + kk) * stride + col0 + nn];
                }
                TBAR(barid);
                #pragma unroll 16
                for (int kk = 0; kk < 64; kk++) {
                    ulonglong2 wv = *reinterpret_cast<const ulonglong2*>(&Ws[kk * 64 + ptx * 4]);
                    #pragma unroll
                    for (int i = 0; i < 4; i++) {
                        float xv = xs[(pty * 4 + i) * 65 + kk];
                        unsigned long long xx = pack2(xv, xv);
                        fma2(acc01[i], xx, wv.x);
                        fma2(acc23[i], xx, wv.y);
                    }
                }
            }
            float a[4][4];
            #pragma unroll
            for (int i = 0; i < 4; i++) {
                unpack2(acc01[i], a[i][0], a[i][1]);
                unpack2(acc23[i], a[i][2], a[i][3]);
            }
            #pragma unroll
            for (int j = 0; j < 4; j++) {
                int n = nt * 64 + ptx * 4 + j;
                float4 v = make_float4(a[0][j], a[1][j], a[2][j], a[3][j]);
                *reinterpret_cast<float4*>(&g_Z[((size_t)t * NZt + n) * Bb + pty * 4]) = v;
            }
        }
    }
    NBAR();
    if (tid == 0) {
        atom_add_rel(&g_zdone.v);
        while (ld_acq(&g_zdone.v) < (R + 1u) * (unsigned)NBLK) { }
    }
    NBAR();

    // ================= load duplicated U slice (once) =================
    const int u0 = bid * 4;
    const int m0 = (bid - NUBLK) * 8;
    {
        const int c = tid & 15, kk0 = tid >> 4;
        if (!isE) {
            const float* Ug;
            switch (c >> 2) {
                case 0:  Ug = Ui; break;
                case 1:  Ug = Uf; break;
                case 2:  Ug = Uo; break;
                default: Ug = Uc; break;
            }
            const int lc = u0 + (c & 3);
            for (int k = kk0; k < Uu; k += 32) {
                float v = Ug[(size_t)k * Uu + lc];
                Ud[k * 32 + c * 2] = v;
                Ud[k * 32 + c * 2 + 1] = v;
            }
        } else {
            for (int k = kk0; k < Uu; k += 32) {
                float v = (c < 8) ? Ue[(size_t)k * Mm + m0 + c] : 0.f;
                Ud[k * 32 + c * 2] = v;
                Ud[k * 32 + c * 2 + 1] = v;
            }
        }
    }
    NBAR();

    // ================= PHASE B: recurrence =================
    const int s    = tid >> 5;
    const int lidw = tid & 31;
    const int bgrp = lidw & 7, cgrp = lidw >> 3;
    const int kbase = s * 32;
    const int rc = tid >> 5, rb = tid & 31;
    const int p2h = tid >> 8;
    const int item = tid & 255;
    const uint32_t fdst = smem_u + (uint32_t)(OFF_HT + tid * 36) * 4;

    int zcol; bool zvalid;
    if (!isE) { zcol = (rc >> 2) * Uu + u0 + (rc & 3); zvalid = true; }
    else      { zvalid = (rc < 8); zcol = 4 * Uu + m0 + (zvalid ? rc : 0); }

    for (int t = 0; t < Tt; t++) {
        float z0 = 0.f, z1 = 0.f;
        if (zvalid) {
            const float* zp = &g_Z[((size_t)t * NZt + zcol) * Bb];
            z0 = __ldcs(zp + rb);
            z1 = __ldcs(zp + 32 + rb);
        }

        if (t > 0) {
            if (tid == 0) { while (ld_acq_sh(&gf[0]) < (unsigned)t) { } }
            NBAR();

            const float* hsrc = &g_hTT[t & 1][0][0];

            #pragma unroll
            for (int bh = 0; bh < 2; bh++) {
                {
                    const float* src = hsrc + (size_t)tid * Bb + bh * 32;
                    #pragma unroll
                    for (int j = 0; j < 8; j++) cp16(fdst + j * 16, src + j * 4);
                    cp_commit();
                    cp_wait0();
                }
                NBAR();

                unsigned long long acc[2][4];
                #pragma unroll
                for (int i = 0; i < 2; i++)
                    #pragma unroll
                    for (int j = 0; j < 4; j++) acc[i][j] = 0ull;

                const float* hp = &hT[kbase * 36 + bgrp * 4];
                const float* up = &Ud[kbase * 32 + cgrp * 8];
                #pragma unroll 8
                for (int k = 0; k < 32; k++) {
                    ulonglong2 hv  = *reinterpret_cast<const ulonglong2*>(hp + k * 36);
                    ulonglong2 u01 = *reinterpret_cast<const ulonglong2*>(up + k * 32);
                    ulonglong2 u23 = *reinterpret_cast<const ulonglong2*>(up + k * 32 + 4);
                    fma2(acc[0][0], hv.x, u01.x);
                    fma2(acc[0][1], hv.x, u01.y);
                    fma2(acc[0][2], hv.x, u23.x);
                    fma2(acc[0][3], hv.x, u23.y);
                    fma2(acc[1][0], hv.y, u01.x);
                    fma2(acc[1][1], hv.y, u01.y);
                    fma2(acc[1][2], hv.y, u23.x);
                    fma2(acc[1][3], hv.y, u23.y);
                }
                NBAR();

                #pragma unroll
                for (int j = 0; j < 4; j++) {
                    const int base = (s * 16 + cgrp * 4 + j) * 36 + bgrp * 4;
                    *reinterpret_cast<unsigned long long*>(&ps2[base])     = acc[0][j];
                    *reinterpret_cast<unsigned long long*>(&ps2[base + 2]) = acc[1][j];
                }
                NBAR();

                {
                    float v = 0.f;
                    #pragma unroll
                    for (int s2 = 0; s2 < 16; s2++)
                        v += ps2[(s2 * 16 + rc) * 36 + rb];
                    float zz = bh ? z1 : z0;
                    if (!isE)
                        zt[rc * 65 + bh * 32 + rb] = v + zz;
                    else if (zvalid)
                        g_ze[bh * 32 + rb][m0 + rc] = v + zz;
                }
                NBAR();
            }
        } else {
            if (!isE) {
                zt[rc * 65 + rb]      = z0;
                zt[rc * 65 + 32 + rb] = z1;
            } else if (zvalid) {
                g_ze[rb][m0 + rc]      = z0;
                g_ze[32 + rb][m0 + rc] = z1;
            }
            NBAR();
        }

        if (isE) {
            // ---- arrival: ze cols done; last e-block broadcasts ze epoch ----
            if (tid == 0) {
                MEMBAR_GL();
                unsigned old = atom_add_rel(&g_ecnt1.v);
                if (old == EB + 8u * (unsigned)(t + 1) - 1u) {
                    #pragma unroll
                    for (int i = 0; i < 8; i++)
                        st_rel_g(&g_zmail[i].v, EPB + (unsigned)(t + 1));
                }
                while (ld_acq_sh(&gf[2]) < (unsigned)(t + 1)) { }
            }
            NBAR();
            // ---- softmax for this e-block's 8 batch rows ----
            if (tid < 256) {
                const int w = tid >> 5, lane = tid & 31;
                const int b = (bid - NUBLK) * 8 + w;
                float v0 = __ldcg(&g_ze[b][lane]);
                float v1 = __ldcg(&g_ze[b][lane + 32]);
                float mx = fmaxf(v0, v1);
                #pragma unroll
                for (int d = 16; d; d >>= 1) mx = fmaxf(mx, __shfl_xor_sync(0xffffffffu, mx, d));
                float e0 = __expf(v0 - mx), e1 = __expf(v1 - mx);
                float sum = e0 + e1;
                #pragma unroll
                for (int d = 16; d; d >>= 1) sum += __shfl_xor_sync(0xffffffffu, sum, d);
                float inv = __fdividef(1.f, sum);
                g_eprob[b][lane]      = e0 * inv;
                g_eprob[b][lane + 32] = e1 * inv;
            }
            NBAR();
            if (tid == 0) {
                MEMBAR_GL();
                unsigned old = atom_add_rel(&g_ecnt2.v);
                if (old == EB + 8u * (unsigned)(t + 1) - 1u) {
                    #pragma unroll 4
                    for (int i = 0; i < 32; i++)
                        st_rel_g(&g_pmail[i].v, EPB + (unsigned)(t + 1));
                }
            }
            continue;
        }

        // ---- u-blocks: activations early (registers), overlapped with eprob wait ----
        float iv = 0.f, fv = 0.f, ov = 0.f, cv = 0.f;
        if (tid < 256) {
            const int uul = tid >> 6, b = tid & 63;
            float zi = zt[(uul)      * 65 + b];
            float zf = zt[(4 + uul)  * 65 + b];
            float zo = zt[(8 + uul)  * 65 + b];
            float zc = zt[(12 + uul) * 65 + b];
            iv = __fdividef(1.f, 1.f + __expf(-zi));
            fv = __fdividef(1.f, 1.f + __expf(-zf));
            ov = __fdividef(1.f, 1.f + __expf(-zo));
            float t2 = __expf(2.f * zc);
            cv = __fdividef(t2 - 1.f, t2 + 1.f);
        }
        if (tid == 0) { while (ld_acq_sh(&gf[1]) < (unsigned)(t + 1)) { } }
        NBAR();

        // ---- load probabilities (coalesced float4 from L2) ----
        #pragma unroll
        for (int l = 0; l < 2; l++) {
            int idx = l * 512 + tid;
            float4 v = __ldcg(reinterpret_cast<const float4*>(&g_eprob[0][0]) + idx);
            int b = idx >> 4, m = (idx & 15) * 4;
            zes[b * 65 + m]     = v.x;
            zes[b * 65 + m + 1] = v.y;
            zes[b * 65 + m + 2] = v.z;
            zes[b * 65 + m + 3] = v.w;
        }
        NBAR();

        // ---- phase 2: memory read (m split across halves) + update ----
        {
            const int uul = item >> 6, b = item & 63;
            const int mlim = (t < 64) ? t : 64;
            const int lo = p2h * 32;
            const int hi = (mlim < lo + 32) ? mlim : lo + 32;
            float p = 0.f;
            const float* zr = &zes[b * 65];
            #pragma unroll 4
            for (int m = lo; m < hi; m++)
                p += zr[m] * cr[(((t - 1 - m) & 63) * 4 + uul) * 64 + b];
            if (p2h == 1) psb[item] = p;
            NBAR();
            if (p2h == 0) {
                float mc = p + psb[item];
                float c = fv * mc + iv * cv;
                float t2c = __expf(2.f * c);
                float th = __fdividef(t2c - 1.f, t2c + 1.f);
                float h = ov * th;
                cr[((t & 63) * 4 + uul) * 64 + b] = c;
                hst[uul * 64 + b] = h;
            }
        }
        NBAR();
        // ---- stores: out (by b) + transposed h (by u row) ----
        if (tid < 64) {
            const int b = tid;
            float4 hv = make_float4(hst[b], hst[64 + b], hst[128 + b], hst[192 + b]);
            *reinterpret_cast<float4*>(&out[((size_t)b * Tt + t) * Uu + u0]) = hv;
        } else if (tid < 128) {
            const int r = tid - 64, uul = r >> 4, seg = r & 15;
            float4 hv = *reinterpret_cast<const float4*>(&hst[uul * 64 + seg * 4]);
            *reinterpret_cast<float4*>(&g_hTT[(t + 1) & 1][u0 + uul][seg * 4]) = hv;
        }
        NBAR();
        // ---- arrival: last u-block broadcasts h epoch ----
        if (tid == 0) {
            MEMBAR_GL();
            unsigned old = atom_add_rel(&g_hcnt.v);
            if (old == HB + 128u * (unsigned)(t + 1) - 1u) {
                #pragma unroll 2
                for (int i = 0; i < 34; i++)
                    st_rel_g(&g_hmail[i].v, EPB + (unsigned)(t + 1));
            }
        }
    }
}

// ---------------- launch: ONE kernel ----------------
extern "C" void kernel_launch(void* const* d_in, const int* in_sizes, int n_in,
                              void* d_out, int out_size) {
    (void)in_sizes; (void)n_in; (void)out_size;
    const float* x  = (const float*)d_in[0];
    const float* Wi = (const float*)d_in[1];
    const float* Ui = (const float*)d_in[2];
    const float* bi = (const float*)d_in[3];
    const float* Wf = (const float*)d_in[4];
    const float* Uf = (const float*)d_in[5];
    const float* bf = (const float*)d_in[6];
    const float* Wo = (const float*)d_in[7];
    const float* Uo = (const float*)d_in[8];
    const float* bo = (const float*)d_in[9];
    const float* Wc = (const float*)d_in[10];
    const float* Uc = (const float*)d_in[11];
    const float* bc = (const float*)d_in[12];
    const float* We = (const float*)d_in[13];
    const float* Ue = (const float*)d_in[14];
    const float* be = (const float*)d_in[15];
    float* out = (float*)d_out;

    const size_t SMEM = (size_t)SMEM_F * sizeof(float);   // 227712 B
    cudaFuncSetAttribute(xlstm_kernel, cudaFuncAttributeMaxDynamicSharedMemorySize, (int)SMEM);

    xlstm_kernel<<<NBLK, NTHR, SMEM>>>(out, x,
        Wi, Wf, Wo, Wc, We, bi, bf, bo, bc, be,
        Ui, Uf, Uo, Uc, Ue);
}

// round 13
// speedup vs baseline: 1.6308x; 1.6308x over previous
#include <cuda_runtime.h>
#include <math.h>
#include <stdint.h>

// Problem constants
#define Tt   512
#define Bb   64
#define Dd   256
#define Uu   512
#define Mm   64
#define NZt  2112   // 4*U + M

#define NUBLK 128   // u-blocks: 4 u-cols each (16 z-cols)
#define NEBLK 8     // e-blocks: 8 e-cols each
#define NBLK  136
#define NTHR  544   // 512 main threads + 1 gate warp
#define NTILES (33 * 512)

// ---------------- device scratch (free-running across graph replays) ----------------
__device__ float g_Z[(size_t)Tt * NZt * Bb];   // Z[t][n][b]
__device__ float g_hTT[2][Uu][Bb];             // hidden state TRANSPOSED [u][b], double buffered
__device__ float g_ze[Bb][Mm];                 // pre-softmax e logits
__device__ float g_cr[NUBLK][Mm][4][Bb];       // per-u-block c-ring (L2-resident, 8.4MB)

struct __align__(128) Cnt { unsigned int v; unsigned int pad[31]; };
__device__ Cnt g_hcnt;        // h arrivals (128/step)
__device__ Cnt g_ecnt;        // ze arrivals (8/step)
__device__ Cnt g_zdone;       // Z-phase barrier (+136 per replay)
__device__ Cnt g_tix;         // replay ticket counter (+136 per replay)

// SMEM float offsets
#define OFF_UD   0            // U duplicated [512 k][32] = 16384
#define OFF_HT0  16384        // hT buf0 [512 k][36] = 18432 (ps2/zes/zt alias inside)
#define OFF_PS2  16384        //   alias: split-K partials (9216 floats)
#define OFF_ZES  25600        //   alias: probs [64 b][65] = 4160
#define OFF_ZT   29760        //   alias: zt [16 c][65] = 1040 (ends 30800 < 34816)
#define OFF_HT1  34816        // hT buf1 [512 k][36] = 18432 (ends 53248)
#define OFF_HST  53248        // h staging [4 uul][64 b] = 256
#define OFF_PSB  53504        // phase2 partial buffer [256]
#define OFF_GF   53760        // flags: 0=h ready t, 1=ze ready t+1
#define SMEM_F   53776        // 215104 bytes
// Z-phase scratch (overlaps UD/HT0, used strictly before them)
#define OFF_XS0  0
#define OFF_WS0  4160
#define OFF_XS1  8256
#define OFF_WS1  12416

// ---------------- PTX helpers ----------------
__device__ __forceinline__ void cp16(uint32_t dst, const float* src) {
    asm volatile("cp.async.cg.shared.global [%0], [%1], 16;" :: "r"(dst), "l"(src));
}
__device__ __forceinline__ void cp_commit() { asm volatile("cp.async.commit_group;"); }
__device__ __forceinline__ void cp_wait0()  { asm volatile("cp.async.wait_group 0;"); }
__device__ __forceinline__ void cp_wait1()  { asm volatile("cp.async.wait_group 1;"); }
__device__ __forceinline__ unsigned ld_acq(const unsigned int* p) {
    unsigned v;
    asm volatile("ld.acquire.gpu.global.u32 %0, [%1];" : "=r"(v) : "l"(p));
    return v;
}
__device__ __forceinline__ void red_rel(unsigned int* p) {
    asm volatile("red.release.gpu.global.add.u32 [%0], 1;" :: "l"(p));
}
__device__ __forceinline__ unsigned ld_acq_sh(const unsigned int* p) {
    unsigned v, a = (unsigned)__cvta_generic_to_shared(p);
    asm volatile("ld.acquire.cta.shared.u32 %0, [%1];" : "=r"(v) : "r"(a));
    return v;
}
__device__ __forceinline__ void st_rel_sh(unsigned int* p, unsigned v) {
    unsigned a = (unsigned)__cvta_generic_to_shared(p);
    asm volatile("st.release.cta.shared.u32 [%0], %1;" :: "r"(a), "r"(v));
}
#define MEMBAR_GL() asm volatile("membar.gl;" ::: "memory")
#define NBAR() asm volatile("bar.sync 1, 512;" ::: "memory")
#define TBAR(id) asm volatile("bar.sync %0, 256;" :: "r"(id) : "memory")

// packed fp32x2 FMA (FFMA2)
__device__ __forceinline__ unsigned long long pack2(float a, float b) {
    unsigned long long r;
    asm("mov.b64 %0, {%1, %2};" : "=l"(r) : "f"(a), "f"(b));
    return r;
}
__device__ __forceinline__ void fma2(unsigned long long& d,
                                     unsigned long long a, unsigned long long b) {
    asm("fma.rn.f32x2 %0, %1, %2, %0;" : "+l"(d) : "l"(a), "l"(b));
}
__device__ __forceinline__ void unpack2(unsigned long long v, float& a, float& b) {
    asm("mov.b64 {%0, %1}, %2;" : "=f"(a), "=f"(b) : "l"(v));
}

// ================= single fused kernel =================
__global__ __launch_bounds__(NTHR, 1) void xlstm_kernel(
    float* __restrict__ out, const float* __restrict__ x,
    const float* __restrict__ Wi, const float* __restrict__ Wf,
    const float* __restrict__ Wo, const float* __restrict__ Wc,
    const float* __restrict__ We,
    const float* __restrict__ bi, const float* __restrict__ bf,
    const float* __restrict__ bo, const float* __restrict__ bc,
    const float* __restrict__ be,
    const float* __restrict__ Ui, const float* __restrict__ Uf,
    const float* __restrict__ Uo, const float* __restrict__ Uc,
    const float* __restrict__ Ue)
{
    extern __shared__ float sm[];
    float* Ud  = sm + OFF_UD;
    float* ps2 = sm + OFF_PS2;
    float* zt  = sm + OFF_ZT;
    float* zes = sm + OFF_ZES;
    float* hst = sm + OFF_HST;
    float* psb = sm + OFF_PSB;
    unsigned int* gf = (unsigned int*)(sm + OFF_GF);
    __shared__ unsigned sR;

    const uint32_t smem_u = (uint32_t)__cvta_generic_to_shared(sm);
    const int bid = blockIdx.x;
    const int tid = threadIdx.x;
    const bool isE = (bid >= NUBLK);

    if (tid == 0) {
        unsigned old = atomicAdd(&g_tix.v, 1u);
        sR = old / (unsigned)NBLK;
    }
    if (tid < 16) gf[tid] = 0u;
    __syncthreads();
    const unsigned R = sR;
    const unsigned HB = R * 65536u;       // h counter base (128*512)
    const unsigned EB = R * 4096u;        // e counter base (8*512)

    // ======== gate warp (tids 512..543) ========
    if (tid >= 512) {
        const int lane = tid - 512;
        if (lane == 0) {
            for (int s = 1; s < Tt; s++) {
                while (ld_acq(&g_hcnt.v) < HB + 128u * (unsigned)s) { }
                st_rel_sh(&gf[0], (unsigned)s);
            }
        } else if (lane == 1 && !isE) {
            for (int t = 0; t < Tt; t++) {
                while (ld_acq(&g_ecnt.v) < EB + 8u * (unsigned)(t + 1)) { }
                st_rel_sh(&gf[1], (unsigned)(t + 1));
            }
        }
        return;
    }

    // ================= PHASE A: precompute Z =================
    {
        const int team = tid >> 8;
        const int ttid = tid & 255;
        float* xs = sm + (team ? OFF_XS1 : OFF_XS0);
        float* Ws = sm + (team ? OFF_WS1 : OFF_WS0);
        const int barid = 2 + team;
        const int ptx = ttid & 15, pty = ttid >> 4;

        for (int tile = bid * 2 + team; tile < NTILES; tile += NBLK * 2) {
            const int t  = tile / 33;
            const int nt = tile % 33;
            const float* W; const float* bv;
            switch (nt >> 3) {
                case 0:  W = Wi; bv = bi; break;
                case 1:  W = Wf; bv = bf; break;
                case 2:  W = Wo; bv = bo; break;
                case 3:  W = Wc; bv = bc; break;
                default: W = We; bv = be; break;
            }
            const int stride = (nt < 32) ? Uu : Mm;
            const int col0   = (nt & 7) * 64;

            unsigned long long acc01[4], acc23[4];
            {
                unsigned long long p01 = pack2(bv[col0 + ptx * 4 + 0], bv[col0 + ptx * 4 + 1]);
                unsigned long long p23 = pack2(bv[col0 + ptx * 4 + 2], bv[col0 + ptx * 4 + 3]);
                #pragma unroll
                for (int i = 0; i < 4; i++) { acc01[i] = p01; acc23[i] = p23; }
            }
            for (int kb = 0; kb < 4; kb++) {
                TBAR(barid);
                #pragma unroll
                for (int l = 0; l < 16; l++) {
                    int idx = l * 256 + ttid;
                    int b = idx >> 6, kk = idx & 63;
                    xs[b * 65 + kk] = x[(size_t)b * Tt * Dd + (size_t)t * Dd + kb * 64 + kk];
                }
                #pragma unroll
                for (int l = 0; l < 16; l++) {
                    int idx = l * 256 + ttid;
                    int kk = idx >> 6, nn = idx & 63;
                    Ws[kk * 64 + nn] = W[(size_t)(kb * 64 + kk) * stride + col0 + nn];
                }
                TBAR(barid);
                #pragma unroll 16
                for (int kk = 0; kk < 64; kk++) {
                    ulonglong2 wv = *reinterpret_cast<const ulonglong2*>(&Ws[kk * 64 + ptx * 4]);
                    #pragma unroll
                    for (int i = 0; i < 4; i++) {
                        float xv = xs[(pty * 4 + i) * 65 + kk];
                        unsigned long long xx = pack2(xv, xv);
                        fma2(acc01[i], xx, wv.x);
                        fma2(acc23[i], xx, wv.y);
                    }
                }
            }
            float a[4][4];
            #pragma unroll
            for (int i = 0; i < 4; i++) {
                unpack2(acc01[i], a[i][0], a[i][1]);
                unpack2(acc23[i], a[i][2], a[i][3]);
            }
            #pragma unroll
            for (int j = 0; j < 4; j++) {
                int n = nt * 64 + ptx * 4 + j;
                float4 v = make_float4(a[0][j], a[1][j], a[2][j], a[3][j]);
                *reinterpret_cast<float4*>(&g_Z[((size_t)t * NZt + n) * Bb + pty * 4]) = v;
            }
        }
    }
    NBAR();
    if (tid == 0) {
        MEMBAR_GL();
        red_rel(&g_zdone.v);
        while (ld_acq(&g_zdone.v) < (R + 1u) * (unsigned)NBLK) { }
    }
    NBAR();

    // ================= load duplicated U slice (once) =================
    const int u0 = bid * 4;
    const int m0 = (bid - NUBLK) * 8;
    {
        const int c = tid & 15, kk0 = tid >> 4;
        if (!isE) {
            const float* Ug;
            switch (c >> 2) {
                case 0:  Ug = Ui; break;
                case 1:  Ug = Uf; break;
                case 2:  Ug = Uo; break;
                default: Ug = Uc; break;
            }
            const int lc = u0 + (c & 3);
            for (int k = kk0; k < Uu; k += 32) {
                float v = Ug[(size_t)k * Uu + lc];
                Ud[k * 32 + c * 2] = v;
                Ud[k * 32 + c * 2 + 1] = v;
            }
        } else {
            for (int k = kk0; k < Uu; k += 32) {
                float v = (c < 8) ? Ue[(size_t)k * Mm + m0 + c] : 0.f;
                Ud[k * 32 + c * 2] = v;
                Ud[k * 32 + c * 2 + 1] = v;
            }
        }
    }
    NBAR();

    // ================= PHASE B: recurrence =================
    const int s    = tid >> 5;
    const int lidw = tid & 31;
    const int bgrp = lidw & 7, cgrp = lidw >> 3;
    const int kbase = s * 32;
    const int rc = tid >> 5, rb = tid & 31;
    const int p2h = tid >> 8;
    const int item = tid & 255;
    const uint32_t fdst0 = smem_u + (uint32_t)(OFF_HT0 + tid * 36) * 4;
    const uint32_t fdst1 = smem_u + (uint32_t)(OFF_HT1 + tid * 36) * 4;
    float* crb = &g_cr[isE ? 0 : bid][0][0][0];

    int zcol; bool zvalid;
    if (!isE) { zcol = (rc >> 2) * Uu + u0 + (rc & 3); zvalid = true; }
    else      { zvalid = (rc < 8); zcol = 4 * Uu + m0 + (zvalid ? rc : 0); }

    for (int t = 0; t < Tt; t++) {
        float z0 = 0.f, z1 = 0.f;
        if (zvalid) {
            const float* zp = &g_Z[((size_t)t * NZt + zcol) * Bb];
            z0 = __ldcs(zp + rb);
            z1 = __ldcs(zp + 32 + rb);
        }

        if (t > 0) {
            if (tid == 0) { while (ld_acq_sh(&gf[0]) < (unsigned)t) { } }
            NBAR();

            const float* src = &g_hTT[t & 1][0][0] + (size_t)tid * Bb;
            // issue BOTH b-half fills (bh1 overlaps bh0 compute)
            #pragma unroll
            for (int j = 0; j < 8; j++) cp16(fdst0 + j * 16, src + j * 4);
            cp_commit();
            #pragma unroll
            for (int j = 0; j < 8; j++) cp16(fdst1 + j * 16, src + 32 + j * 4);
            cp_commit();
            cp_wait1();
            NBAR();                              // hT0 ready

            #pragma unroll
            for (int bh = 0; bh < 2; bh++) {
                unsigned long long acc[2][4];
                #pragma unroll
                for (int i = 0; i < 2; i++)
                    #pragma unroll
                    for (int j = 0; j < 4; j++) acc[i][j] = 0ull;

                const float* hp = sm + (bh ? OFF_HT1 : OFF_HT0) + kbase * 36 + bgrp * 4;
                const float* up = &Ud[kbase * 32 + cgrp * 8];
                #pragma unroll 8
                for (int k = 0; k < 32; k++) {
                    ulonglong2 hv  = *reinterpret_cast<const ulonglong2*>(hp + k * 36);
                    ulonglong2 u01 = *reinterpret_cast<const ulonglong2*>(up + k * 32);
                    ulonglong2 u23 = *reinterpret_cast<const ulonglong2*>(up + k * 32 + 4);
                    fma2(acc[0][0], hv.x, u01.x);
                    fma2(acc[0][1], hv.x, u01.y);
                    fma2(acc[0][2], hv.x, u23.x);
                    fma2(acc[0][3], hv.x, u23.y);
                    fma2(acc[1][0], hv.y, u01.x);
                    fma2(acc[1][1], hv.y, u01.y);
                    fma2(acc[1][2], hv.y, u23.x);
                    fma2(acc[1][3], hv.y, u23.y);
                }
                NBAR();                          // hT0 reads done -> ps2 alias safe

                #pragma unroll
                for (int j = 0; j < 4; j++) {
                    const int base = (s * 16 + cgrp * 4 + j) * 36 + bgrp * 4;
                    *reinterpret_cast<unsigned long long*>(&ps2[base])     = acc[0][j];
                    *reinterpret_cast<unsigned long long*>(&ps2[base + 2]) = acc[1][j];
                }
                NBAR();

                {
                    float v = 0.f;
                    #pragma unroll
                    for (int s2 = 0; s2 < 16; s2++)
                        v += ps2[(s2 * 16 + rc) * 36 + rb];
                    float zz = bh ? z1 : z0;
                    if (!isE)
                        zt[rc * 65 + bh * 32 + rb] = v + zz;
                    else if (zvalid)
                        g_ze[bh * 32 + rb][m0 + rc] = v + zz;
                }
                if (bh == 0) cp_wait0();         // hT1 landed during bh0 compute
                NBAR();                          // ps2 reads done; hT1 visible
            }
        } else {
            if (!isE) {
                zt[rc * 65 + rb]      = z0;
                zt[rc * 65 + 32 + rb] = z1;
            } else if (zvalid) {
                g_ze[rb][m0 + rc]      = z0;
                g_ze[32 + rb][m0 + rc] = z1;
            }
            NBAR();
        }

        if (isE) {
            if (tid == 0) { MEMBAR_GL(); red_rel(&g_ecnt.v); }
            continue;
        }

        // ---- u-blocks: activations early (registers), overlapped with e wait ----
        float iv = 0.f, fv = 0.f, ov = 0.f, cv = 0.f;
        if (tid < 256) {
            const int uul = tid >> 6, b = tid & 63;
            float zi = zt[(uul)      * 65 + b];
            float zf = zt[(4 + uul)  * 65 + b];
            float zo = zt[(8 + uul)  * 65 + b];
            float zc = zt[(12 + uul) * 65 + b];
            iv = __fdividef(1.f, 1.f + __expf(-zi));
            fv = __fdividef(1.f, 1.f + __expf(-zf));
            ov = __fdividef(1.f, 1.f + __expf(-zo));
            float t2 = __expf(2.f * zc);
            cv = __fdividef(t2 - 1.f, t2 + 1.f);
        }
        if (tid == 0) { while (ld_acq_sh(&gf[1]) < (unsigned)(t + 1)) { } }
        NBAR();

        // ---- local softmax: 8 lanes per batch row, direct from L2 ----
        {
            const int sb = tid >> 3, sq = tid & 7;
            const float4* zrow = reinterpret_cast<const float4*>(&g_ze[sb][sq * 8]);
            float4 v0 = __ldcg(zrow);
            float4 v1 = __ldcg(zrow + 1);
            float v[8] = {v0.x, v0.y, v0.z, v0.w, v1.x, v1.y, v1.z, v1.w};
            float mx = -1e30f;
            #pragma unroll
            for (int i = 0; i < 8; i++) mx = fmaxf(mx, v[i]);
            mx = fmaxf(mx, __shfl_xor_sync(0xffffffffu, mx, 1));
            mx = fmaxf(mx, __shfl_xor_sync(0xffffffffu, mx, 2));
            mx = fmaxf(mx, __shfl_xor_sync(0xffffffffu, mx, 4));
            float sum = 0.f;
            #pragma unroll
            for (int i = 0; i < 8; i++) { v[i] = __expf(v[i] - mx); sum += v[i]; }
            sum += __shfl_xor_sync(0xffffffffu, sum, 1);
            sum += __shfl_xor_sync(0xffffffffu, sum, 2);
            sum += __shfl_xor_sync(0xffffffffu, sum, 4);
            float inv = __fdividef(1.f, sum);
            #pragma unroll
            for (int i = 0; i < 8; i++) zes[sb * 65 + sq * 8 + i] = v[i] * inv;
        }
        NBAR();

        // ---- phase 2: memory read from global c-ring (m split across halves) ----
        {
            const int uul = item >> 6, b = item & 63;
            const int lo = p2h * 32;
            float p = 0.f;
            const float* zr = &zes[b * 65];
            if (t >= 64) {
                #pragma unroll
                for (int mm = 0; mm < 32; mm++) {
                    int m = lo + mm;
                    int slot = (t - 1 - m) & 63;
                    p += zr[m] * crb[slot * 256 + uul * 64 + b];
                }
            } else {
                const int hi = (t < lo + 32) ? t : lo + 32;
                for (int m = lo; m < hi; m++) {
                    int slot = (t - 1 - m) & 63;
                    p += zr[m] * crb[slot * 256 + uul * 64 + b];
                }
            }
            if (p2h == 1) psb[item] = p;
            NBAR();
            if (p2h == 0) {
                float mc = p + psb[item];
                float c = fv * mc + iv * cv;
                float t2c = __expf(2.f * c);
                float th = __fdividef(t2c - 1.f, t2c + 1.f);
                float h = ov * th;
                crb[(t & 63) * 256 + uul * 64 + b] = c;
                hst[uul * 64 + b] = h;
            }
        }
        NBAR();
        // ---- stores: out (by b) + transposed h (by u row) ----
        if (tid < 64) {
            const int b = tid;
            float4 hv = make_float4(hst[b], hst[64 + b], hst[128 + b], hst[192 + b]);
            *reinterpret_cast<float4*>(&out[((size_t)b * Tt + t) * Uu + u0]) = hv;
        } else if (tid < 128) {
            const int r = tid - 64, uul = r >> 4, seg = r & 15;
            float4 hv = *reinterpret_cast<const float4*>(&hst[uul * 64 + seg * 4]);
            *reinterpret_cast<float4*>(&g_hTT[(t + 1) & 1][u0 + uul][seg * 4]) = hv;
        }
        NBAR();
        if (tid == 0) { MEMBAR_GL(); red_rel(&g_hcnt.v); }
    }
}

// ---------------- launch: ONE kernel ----------------
extern "C" void kernel_launch(void* const* d_in, const int* in_sizes, int n_in,
                              void* d_out, int out_size) {
    (void)in_sizes; (void)n_in; (void)out_size;
    const float* x  = (const float*)d_in[0];
    const float* Wi = (const float*)d_in[1];
    const float* Ui = (const float*)d_in[2];
    const float* bi = (const float*)d_in[3];
    const float* Wf = (const float*)d_in[4];
    const float* Uf = (const float*)d_in[5];
    const float* bf = (const float*)d_in[6];
    const float* Wo = (const float*)d_in[7];
    const float* Uo = (const float*)d_in[8];
    const float* bo = (const float*)d_in[9];
    const float* Wc = (const float*)d_in[10];
    const float* Uc = (const float*)d_in[11];
    const float* bc = (const float*)d_in[12];
    const float* We = (const float*)d_in[13];
    const float* Ue = (const float*)d_in[14];
    const float* be = (const float*)d_in[15];
    float* out = (float*)d_out;

    const size_t SMEM = (size_t)SMEM_F * sizeof(float);   // 215104 B
    cudaFuncSetAttribute(xlstm_kernel, cudaFuncAttributeMaxDynamicSharedMemorySize, (int)SMEM);

    xlstm_kernel<<<NBLK, NTHR, SMEM>>>(out, x,
        Wi, Wf, Wo, Wc, We, bi, bf, bo, bc, be,
        Ui, Uf, Uo, Uc, Ue);
}

// round 14
// speedup vs baseline: 2.0873x; 1.2799x over previous
#include <cuda_runtime.h>
#include <math.h>
#include <stdint.h>

// Problem constants
#define Tt   512
#define Bb   64
#define Dd   256
#define Uu   512
#define Mm   64
#define NZt  2112   // 4*U + M

#define NUBLK 128   // u-blocks: 4 u-cols each (16 z-cols)
#define NEBLK 8     // e-blocks: 8 e-cols each
#define NBLK  136
#define NTHR  544   // 512 main threads + 1 gate warp
#define NTILES (33 * 512)

// ---------------- device scratch (free-running across graph replays) ----------------
__device__ float g_Z[(size_t)Tt * NZt * Bb];   // Z[t][n][b]
__device__ float g_hTT[2][Uu][Bb];             // hidden state TRANSPOSED [u][b], double buffered
__device__ float g_ze[Bb][Mm];                 // pre-softmax e logits

struct __align__(128) Cnt { unsigned int v; unsigned int pad[31]; };
__device__ Cnt g_hep[NUBLK];  // per-u-block h epoch words (value R*512 + t+1)
__device__ Cnt g_eep[NEBLK];  // per-e-block ze epoch words
__device__ Cnt g_zdone;       // Z-phase barrier (+136 per replay)
__device__ Cnt g_tix;         // replay ticket counter (+136 per replay)

// SMEM float offsets (identical to the 9104us best)
#define OFF_UD   0            // U duplicated [512 k][32] = 16384
#define OFF_CR   16384        // cring [64 slot][4 u][64 b] = 16384  (SMEM!)
#define OFF_HT   32768        // hT [512 k][36] = 18432 (ps2 aliases)
#define OFF_ZT   51200        // zt [16 c][65] = 1040
#define OFF_ZES  52240        // probs [64 b][65] = 4160
#define OFF_HST  56400        // h staging [4 uul][64 b] = 256
#define OFF_PSB  56656        // phase2 partial buffer [256]
#define OFF_GF   56912        // flags: 0=h ready t, 1=ze ready t+1
#define SMEM_F   56928        // 227712 bytes
// Z-phase scratch (overlaps UD/CR region, used strictly before them)
#define OFF_XS0  0
#define OFF_WS0  4160
#define OFF_XS1  8256
#define OFF_WS1  12416

// ---------------- PTX helpers ----------------
__device__ __forceinline__ void cp16(uint32_t dst, const float* src) {
    asm volatile("cp.async.cg.shared.global [%0], [%1], 16;" :: "r"(dst), "l"(src));
}
__device__ __forceinline__ void cp_commit() { asm volatile("cp.async.commit_group;"); }
__device__ __forceinline__ void cp_wait0()  { asm volatile("cp.async.wait_group 0;"); }
__device__ __forceinline__ unsigned ld_acq(const unsigned int* p) {
    unsigned v;
    asm volatile("ld.acquire.gpu.global.u32 %0, [%1];" : "=r"(v) : "l"(p));
    return v;
}
__device__ __forceinline__ void red_rel(unsigned int* p) {
    asm volatile("red.release.gpu.global.add.u32 [%0], 1;" :: "l"(p));
}
__device__ __forceinline__ void st_rel_g(unsigned int* p, unsigned v) {
    asm volatile("st.release.gpu.global.u32 [%0], %1;" :: "l"(p), "r"(v));
}
__device__ __forceinline__ unsigned ld_acq_sh(const unsigned int* p) {
    unsigned v, a = (unsigned)__cvta_generic_to_shared(p);
    asm volatile("ld.acquire.cta.shared.u32 %0, [%1];" : "=r"(v) : "r"(a));
    return v;
}
__device__ __forceinline__ void st_rel_sh(unsigned int* p, unsigned v) {
    unsigned a = (unsigned)__cvta_generic_to_shared(p);
    asm volatile("st.release.cta.shared.u32 [%0], %1;" :: "r"(a), "r"(v));
}
#define MEMBAR_GL() asm volatile("membar.gl;" ::: "memory")
#define NBAR() asm volatile("bar.sync 1, 512;" ::: "memory")
#define TBAR(id) asm volatile("bar.sync %0, 256;" :: "r"(id) : "memory")

// packed fp32x2 FMA (FFMA2)
__device__ __forceinline__ unsigned long long pack2(float a, float b) {
    unsigned long long r;
    asm("mov.b64 %0, {%1, %2};" : "=l"(r) : "f"(a), "f"(b));
    return r;
}
__device__ __forceinline__ void fma2(unsigned long long& d,
                                     unsigned long long a, unsigned long long b) {
    asm("fma.rn.f32x2 %0, %1, %2, %0;" : "+l"(d) : "l"(a), "l"(b));
}
__device__ __forceinline__ void unpack2(unsigned long long v, float& a, float& b) {
    asm("mov.b64 {%0, %1}, %2;" : "=f"(a), "=f"(b) : "l"(v));
}

// ================= single fused kernel =================
__global__ __launch_bounds__(NTHR, 1) void xlstm_kernel(
    float* __restrict__ out, const float* __restrict__ x,
    const float* __restrict__ Wi, const float* __restrict__ Wf,
    const float* __restrict__ Wo, const float* __restrict__ Wc,
    const float* __restrict__ We,
    const float* __restrict__ bi, const float* __restrict__ bf,
    const float* __restrict__ bo, const float* __restrict__ bc,
    const float* __restrict__ be,
    const float* __restrict__ Ui, const float* __restrict__ Uf,
    const float* __restrict__ Uo, const float* __restrict__ Uc,
    const float* __restrict__ Ue)
{
    extern __shared__ float sm[];
    float* Ud  = sm + OFF_UD;
    float* cr  = sm + OFF_CR;
    float* hT  = sm + OFF_HT;
    float* ps2 = sm + OFF_HT;          // alias (fenced by NBARs)
    float* zt  = sm + OFF_ZT;
    float* zes = sm + OFF_ZES;
    float* hst = sm + OFF_HST;
    float* psb = sm + OFF_PSB;
    unsigned int* gf = (unsigned int*)(sm + OFF_GF);
    __shared__ unsigned sR;

    const uint32_t smem_u = (uint32_t)__cvta_generic_to_shared(sm);
    const int bid = blockIdx.x;
    const int tid = threadIdx.x;
    const bool isE = (bid >= NUBLK);

    if (tid == 0) {
        unsigned old = atomicAdd(&g_tix.v, 1u);
        sR = old / (unsigned)NBLK;
    }
    if (tid < 16) gf[tid] = 0u;
    __syncthreads();
    const unsigned R = sR;
    const unsigned EPB = R * 512u;        // epoch base

    // ======== gate warp (tids 512..543): parallel epoch polling ========
    if (tid >= 512) {
        const int lane = tid - 512;
        if (lane < 16) {
            // each lane watches 8 u-block epochs; warp-vote then publish
            for (int s2 = 1; s2 < Tt; s2++) {
                const unsigned tgt = EPB + (unsigned)s2;
                bool ok;
                do {
                    ok = true;
                    #pragma unroll
                    for (int j = 0; j < 8; j++)
                        ok &= (ld_acq(&g_hep[lane * 8 + j].v) >= tgt);
                } while (!__all_sync(0x0000FFFFu, ok));
                if (lane == 0) st_rel_sh(&gf[0], (unsigned)s2);
            }
        } else if (lane < 24 && !isE) {
            // each lane watches 1 e-block epoch
            for (int t = 0; t < Tt; t++) {
                const unsigned tgt = EPB + (unsigned)(t + 1);
                bool ok;
                do {
                    ok = (ld_acq(&g_eep[lane - 16].v) >= tgt);
                } while (!__all_sync(0x00FF0000u, ok));
                if (lane == 16) st_rel_sh(&gf[1], (unsigned)(t + 1));
            }
        }
        return;
    }

    // ================= PHASE A: precompute Z =================
    {
        const int team = tid >> 8;
        const int ttid = tid & 255;
        float* xs = sm + (team ? OFF_XS1 : OFF_XS0);
        float* Ws = sm + (team ? OFF_WS1 : OFF_WS0);
        const int barid = 2 + team;
        const int ptx = ttid & 15, pty = ttid >> 4;

        for (int tile = bid * 2 + team; tile < NTILES; tile += NBLK * 2) {
            const int t  = tile / 33;
            const int nt = tile % 33;
            const float* W; const float* bv;
            switch (nt >> 3) {
                case 0:  W = Wi; bv = bi; break;
                case 1:  W = Wf; bv = bf; break;
                case 2:  W = Wo; bv = bo; break;
                case 3:  W = Wc; bv = bc; break;
                default: W = We; bv = be; break;
            }
            const int stride = (nt < 32) ? Uu : Mm;
            const int col0   = (nt & 7) * 64;

            unsigned long long acc01[4], acc23[4];
            {
                unsigned long long p01 = pack2(bv[col0 + ptx * 4 + 0], bv[col0 + ptx * 4 + 1]);
                unsigned long long p23 = pack2(bv[col0 + ptx * 4 + 2], bv[col0 + ptx * 4 + 3]);
                #pragma unroll
                for (int i = 0; i < 4; i++) { acc01[i] = p01; acc23[i] = p23; }
            }
            for (int kb = 0; kb < 4; kb++) {
                TBAR(barid);
                #pragma unroll
                for (int l = 0; l < 16; l++) {
                    int idx = l * 256 + ttid;
                    int b = idx >> 6, kk = idx & 63;
                    xs[b * 65 + kk] = x[(size_t)b * Tt * Dd + (size_t)t * Dd + kb * 64 + kk];
                }
                #pragma unroll
                for (int l = 0; l < 16; l++) {
                    int idx = l * 256 + ttid;
                    int kk = idx >> 6, nn = idx & 63;
                    Ws[kk * 64 + nn] = W[(size_t)(kb * 64 + kk) * stride + col0 + nn];
                }
                TBAR(barid);
                #pragma unroll 16
                for (int kk = 0; kk < 64; kk++) {
                    ulonglong2 wv = *reinterpret_cast<const ulonglong2*>(&Ws[kk * 64 + ptx * 4]);
                    #pragma unroll
                    for (int i = 0; i < 4; i++) {
                        float xv = xs[(pty * 4 + i) * 65 + kk];
                        unsigned long long xx = pack2(xv, xv);
                        fma2(acc01[i], xx, wv.x);
                        fma2(acc23[i], xx, wv.y);
                    }
                }
            }
            float a[4][4];
            #pragma unroll
            for (int i = 0; i < 4; i++) {
                unpack2(acc01[i], a[i][0], a[i][1]);
                unpack2(acc23[i], a[i][2], a[i][3]);
            }
            #pragma unroll
            for (int j = 0; j < 4; j++) {
                int n = nt * 64 + ptx * 4 + j;
                float4 v = make_float4(a[0][j], a[1][j], a[2][j], a[3][j]);
                *reinterpret_cast<float4*>(&g_Z[((size_t)t * NZt + n) * Bb + pty * 4]) = v;
            }
        }
    }
    NBAR();
    if (tid == 0) {
        MEMBAR_GL();
        red_rel(&g_zdone.v);
        while (ld_acq(&g_zdone.v) < (R + 1u) * (unsigned)NBLK) { }
    }
    NBAR();

    // ================= load duplicated U slice (once) =================
    const int u0 = bid * 4;
    const int m0 = (bid - NUBLK) * 8;
    {
        const int c = tid & 15, kk0 = tid >> 4;
        if (!isE) {
            const float* Ug;
            switch (c >> 2) {
                case 0:  Ug = Ui; break;
                case 1:  Ug = Uf; break;
                case 2:  Ug = Uo; break;
                default: Ug = Uc; break;
            }
            const int lc = u0 + (c & 3);
            for (int k = kk0; k < Uu; k += 32) {
                float v = Ug[(size_t)k * Uu + lc];
                Ud[k * 32 + c * 2] = v;
                Ud[k * 32 + c * 2 + 1] = v;
            }
        } else {
            for (int k = kk0; k < Uu; k += 32) {
                float v = (c < 8) ? Ue[(size_t)k * Mm + m0 + c] : 0.f;
                Ud[k * 32 + c * 2] = v;
                Ud[k * 32 + c * 2 + 1] = v;
            }
        }
    }
    NBAR();

    // ================= PHASE B: recurrence =================
    const int s    = tid >> 5;                    // warp = split-K slice
    const int lidw = tid & 31;
    const int bgrp = lidw & 7, cgrp = lidw >> 3;
    const int kbase = s * 32;
    const int rc = tid >> 5, rb = tid & 31;
    const int p2h = tid >> 8;
    const int item = tid & 255;
    const uint32_t fdst = smem_u + (uint32_t)(OFF_HT + tid * 36) * 4;

    int zcol; bool zvalid;
    if (!isE) { zcol = (rc >> 2) * Uu + u0 + (rc & 3); zvalid = true; }
    else      { zvalid = (rc < 8); zcol = 4 * Uu + m0 + (zvalid ? rc : 0); }

    for (int t = 0; t < Tt; t++) {
        float z0 = 0.f, z1 = 0.f;
        if (zvalid) {
            const float* zp = &g_Z[((size_t)t * NZt + zcol) * Bb];
            z0 = __ldcs(zp + rb);
            z1 = __ldcs(zp + 32 + rb);
        }

        if (t > 0) {
            if (tid == 0) { while (ld_acq_sh(&gf[0]) < (unsigned)t) { } }
            NBAR();

            const float* src = &g_hTT[t & 1][0][0] + (size_t)tid * Bb;

            #pragma unroll
            for (int bh = 0; bh < 2; bh++) {
                // ---- WARP-LOCAL fill: warp w fills exactly the rows it reads ----
                #pragma unroll
                for (int j = 0; j < 8; j++) cp16(fdst + j * 16, src + bh * 32 + j * 4);
                cp_commit();
                cp_wait0();
                __syncwarp();

                // ---- compute: 4b x 4c tile over this warp's 32 k ----
                unsigned long long acc[2][4];
                #pragma unroll
                for (int i = 0; i < 2; i++)
                    #pragma unroll
                    for (int j = 0; j < 4; j++) acc[i][j] = 0ull;

                const float* hp = &hT[kbase * 36 + bgrp * 4];
                const float* up = &Ud[kbase * 32 + cgrp * 8];
                #pragma unroll 8
                for (int k = 0; k < 32; k++) {
                    ulonglong2 hv  = *reinterpret_cast<const ulonglong2*>(hp + k * 36);
                    ulonglong2 u01 = *reinterpret_cast<const ulonglong2*>(up + k * 32);
                    ulonglong2 u23 = *reinterpret_cast<const ulonglong2*>(up + k * 32 + 4);
                    fma2(acc[0][0], hv.x, u01.x);
                    fma2(acc[0][1], hv.x, u01.y);
                    fma2(acc[0][2], hv.x, u23.x);
                    fma2(acc[0][3], hv.x, u23.y);
                    fma2(acc[1][0], hv.y, u01.x);
                    fma2(acc[1][1], hv.y, u01.y);
                    fma2(acc[1][2], hv.y, u23.x);
                    fma2(acc[1][3], hv.y, u23.y);
                }
                NBAR();                          // all hT reads done -> ps2 alias safe

                #pragma unroll
                for (int j = 0; j < 4; j++) {
                    const int base = (s * 16 + cgrp * 4 + j) * 36 + bgrp * 4;
                    *reinterpret_cast<unsigned long long*>(&ps2[base])     = acc[0][j];
                    *reinterpret_cast<unsigned long long*>(&ps2[base + 2]) = acc[1][j];
                }
                NBAR();

                {
                    float v = 0.f;
                    #pragma unroll
                    for (int s2 = 0; s2 < 16; s2++)
                        v += ps2[(s2 * 16 + rc) * 36 + rb];
                    float zz = bh ? z1 : z0;
                    if (!isE)
                        zt[rc * 65 + bh * 32 + rb] = v + zz;
                    else if (zvalid)
                        g_ze[bh * 32 + rb][m0 + rc] = v + zz;
                }
                NBAR();                          // ps2 reads done -> next fill safe
            }
        } else {
            if (!isE) {
                zt[rc * 65 + rb]      = z0;
                zt[rc * 65 + 32 + rb] = z1;
            } else if (zvalid) {
                g_ze[rb][m0 + rc]      = z0;
                g_ze[32 + rb][m0 + rc] = z1;
            }
            NBAR();
        }

        if (isE) {
            // parallel arrival: own epoch word, no atomic
            if (tid == 0) st_rel_g(&g_eep[bid - NUBLK].v, EPB + (unsigned)(t + 1));
            continue;
        }

        // ---- u-blocks: activations early (registers), overlapped with e wait ----
        float iv = 0.f, fv = 0.f, ov = 0.f, cv = 0.f;
        if (tid < 256) {
            const int uul = tid >> 6, b = tid & 63;
            float zi = zt[(uul)      * 65 + b];
            float zf = zt[(4 + uul)  * 65 + b];
            float zo = zt[(8 + uul)  * 65 + b];
            float zc = zt[(12 + uul) * 65 + b];
            iv = __fdividef(1.f, 1.f + __expf(-zi));
            fv = __fdividef(1.f, 1.f + __expf(-zf));
            ov = __fdividef(1.f, 1.f + __expf(-zo));
            float t2 = __expf(2.f * zc);
            cv = __fdividef(t2 - 1.f, t2 + 1.f);
        }
        if (tid == 0) { while (ld_acq_sh(&gf[1]) < (unsigned)(t + 1)) { } }
        NBAR();

        // ---- local softmax: 8 lanes per batch row, direct from L2 ----
        {
            const int sb = tid >> 3, sq = tid & 7;
            const float4* zrow = reinterpret_cast<const float4*>(&g_ze[sb][sq * 8]);
            float4 v0 = __ldcg(zrow);
            float4 v1 = __ldcg(zrow + 1);
            float v[8] = {v0.x, v0.y, v0.z, v0.w, v1.x, v1.y, v1.z, v1.w};
            float mx = -1e30f;
            #pragma unroll
            for (int i = 0; i < 8; i++) mx = fmaxf(mx, v[i]);
            mx = fmaxf(mx, __shfl_xor_sync(0xffffffffu, mx, 1));
            mx = fmaxf(mx, __shfl_xor_sync(0xffffffffu, mx, 2));
            mx = fmaxf(mx, __shfl_xor_sync(0xffffffffu, mx, 4));
            float sum = 0.f;
            #pragma unroll
            for (int i = 0; i < 8; i++) { v[i] = __expf(v[i] - mx); sum += v[i]; }
            sum += __shfl_xor_sync(0xffffffffu, sum, 1);
            sum += __shfl_xor_sync(0xffffffffu, sum, 2);
            sum += __shfl_xor_sync(0xffffffffu, sum, 4);
            float inv = __fdividef(1.f, sum);
            #pragma unroll
            for (int i = 0; i < 8; i++) zes[sb * 65 + sq * 8 + i] = v[i] * inv;
        }
        NBAR();

        // ---- phase 2: memory read from SMEM c-ring (m split across halves) ----
        {
            const int uul = item >> 6, b = item & 63;
            const int lo = p2h * 32;
            float p = 0.f;
            const float* zr = &zes[b * 65];
            if (t >= 64) {
                #pragma unroll
                for (int mm = 0; mm < 32; mm++) {
                    int m = lo + mm;
                    p += zr[m] * cr[(((t - 1 - m) & 63) * 4 + uul) * 64 + b];
                }
            } else {
                const int hi = (t < lo + 32) ? t : lo + 32;
                for (int m = lo; m < hi; m++)
                    p += zr[m] * cr[(((t - 1 - m) & 63) * 4 + uul) * 64 + b];
            }
            if (p2h == 1) psb[item] = p;
            NBAR();
            if (p2h == 0) {
                float mc = p + psb[item];
                float c = fv * mc + iv * cv;
                float t2c = __expf(2.f * c);
                float th = __fdividef(t2c - 1.f, t2c + 1.f);
                float h = ov * th;
                cr[((t & 63) * 4 + uul) * 64 + b] = c;
                hst[uul * 64 + b] = h;
            }
        }
        NBAR();
        // ---- stores: out (by b) + transposed h (by u row) ----
        if (tid < 64) {
            const int b = tid;
            float4 hv = make_float4(hst[b], hst[64 + b], hst[128 + b], hst[192 + b]);
            *reinterpret_cast<float4*>(&out[((size_t)b * Tt + t) * Uu + u0]) = hv;
        } else if (tid < 128) {
            const int r = tid - 64, uul = r >> 4, seg = r & 15;
            float4 hv = *reinterpret_cast<const float4*>(&hst[uul * 64 + seg * 4]);
            *reinterpret_cast<float4*>(&g_hTT[(t + 1) & 1][u0 + uul][seg * 4]) = hv;
        }
        NBAR();
        // parallel arrival: own epoch word, no atomic
        if (tid == 0) st_rel_g(&g_hep[bid].v, EPB + (unsigned)(t + 1));
    }
}

// ---------------- launch: ONE kernel ----------------
extern "C" void kernel_launch(void* const* d_in, const int* in_sizes, int n_in,
                              void* d_out, int out_size) {
    (void)in_sizes; (void)n_in; (void)out_size;
    const float* x  = (const float*)d_in[0];
    const float* Wi = (const float*)d_in[1];
    const float* Ui = (const float*)d_in[2];
    const float* bi = (const float*)d_in[3];
    const float* Wf = (const float*)d_in[4];
    const float* Uf = (const float*)d_in[5];
    const float* bf = (const float*)d_in[6];
    const float* Wo = (const float*)d_in[7];
    const float* Uo = (const float*)d_in[8];
    const float* bo = (const float*)d_in[9];
    const float* Wc = (const float*)d_in[10];
    const float* Uc = (const float*)d_in[11];
    const float* bc = (const float*)d_in[12];
    const float* We = (const float*)d_in[13];
    const float* Ue = (const float*)d_in[14];
    const float* be = (const float*)d_in[15];
    float* out = (float*)d_out;

    const size_t SMEM = (size_t)SMEM_F * sizeof(float);   // 227712 B
    cudaFuncSetAttribute(xlstm_kernel, cudaFuncAttributeMaxDynamicSharedMemorySize, (int)SMEM);

    xlstm_kernel<<<NBLK, NTHR, SMEM>>>(out, x,
        Wi, Wf, Wo, Wc, We, bi, bf, bo, bc, be,
        Ui, Uf, Uo, Uc, Ue);
}

// round 15
// speedup vs baseline: 2.8960x; 1.3874x over previous
#include <cuda_runtime.h>
#include <math.h>
#include <stdint.h>

// Problem constants
#define Tt   512
#define Bb   64
#define Dd   256
#define Uu   512
#define Mm   64
#define NZt  2112   // 4*U + M

#define NUBLK 128   // u-blocks: 4 u-cols each (16 z-cols)
#define NEBLK 8     // e-blocks: 8 e-cols each
#define NBLK  136
#define NTHR  544   // 512 main threads + 1 gate warp
#define NTILES (33 * 512)

// ---------------- device scratch (free-running across graph replays) ----------------
__device__ float g_Z[(size_t)Tt * NZt * Bb];   // Z[t][n][b]
__device__ float g_hTT[2][Uu][Bb];             // hidden state TRANSPOSED [u][b], double buffered
__device__ float g_ze[Bb][Mm];                 // pre-softmax e logits

struct __align__(128) Cnt { unsigned int v; unsigned int pad[31]; };
__device__ Cnt g_hcnt;        // h arrivals (128/step)
__device__ Cnt g_ecnt;        // ze arrivals (8/step)
__device__ Cnt g_zdone;       // Z-phase barrier (+136 per replay)
__device__ Cnt g_tix;         // replay ticket counter (+136 per replay)

// SMEM float offsets
#define OFF_UD   0            // U duplicated [512 k][32] = 16384
#define OFF_CR   16384        // cring [64 slot][4 u][64 b] = 16384 (SMEM)
#define OFF_PS2  32768        // split-K partials [256 rows][68] = 17408
#define OFF_ZT   50176        // zt [16 c][65] = 1040
#define OFF_ZES  51216        // probs [64 b][65] = 4160
#define OFF_HST  55376        // h staging [4 uul][64 b] = 256
#define OFF_PSB  55632        // phase2 partial buffer [256]
#define OFF_GF   55888        // flags: 0=h ready t, 1=ze ready t+1
#define SMEM_F   55904        // 223616 bytes
// Z-phase scratch (overlaps UD/CR head, used strictly before recurrence)
#define OFF_XS0  0
#define OFF_WS0  4160
#define OFF_XS1  8256
#define OFF_WS1  12416

// ---------------- PTX helpers ----------------
__device__ __forceinline__ unsigned ld_acq(const unsigned int* p) {
    unsigned v;
    asm volatile("ld.acquire.gpu.global.u32 %0, [%1];" : "=r"(v) : "l"(p));
    return v;
}
__device__ __forceinline__ void red_rel(unsigned int* p) {
    asm volatile("red.release.gpu.global.add.u32 [%0], 1;" :: "l"(p));
}
__device__ __forceinline__ unsigned ld_acq_sh(const unsigned int* p) {
    unsigned v, a = (unsigned)__cvta_generic_to_shared(p);
    asm volatile("ld.acquire.cta.shared.u32 %0, [%1];" : "=r"(v) : "r"(a));
    return v;
}
__device__ __forceinline__ void st_rel_sh(unsigned int* p, unsigned v) {
    unsigned a = (unsigned)__cvta_generic_to_shared(p);
    asm volatile("st.release.cta.shared.u32 [%0], %1;" :: "r"(a), "r"(v));
}
#define MEMBAR_GL() asm volatile("membar.gl;" ::: "memory")
#define NBAR() asm volatile("bar.sync 1, 512;" ::: "memory")
#define TBAR(id) asm volatile("bar.sync %0, 256;" :: "r"(id) : "memory")

// packed fp32x2 FMA (FFMA2)
__device__ __forceinline__ unsigned long long pack2(float a, float b) {
    unsigned long long r;
    asm("mov.b64 %0, {%1, %2};" : "=l"(r) : "f"(a), "f"(b));
    return r;
}
__device__ __forceinline__ void fma2(unsigned long long& d,
                                     unsigned long long a, unsigned long long b) {
    asm("fma.rn.f32x2 %0, %1, %2, %0;" : "+l"(d) : "l"(a), "l"(b));
}
__device__ __forceinline__ void unpack2(unsigned long long v, float& a, float& b) {
    asm("mov.b64 {%0, %1}, %2;" : "=f"(a), "=f"(b) : "l"(v));
}
// 16B L2-only load (bypasses L1: h is cross-SM mutable)
__device__ __forceinline__ ulonglong2 ldcg2(const void* p) {
    ulonglong2 r;
    asm volatile("ld.global.cg.v2.u64 {%0, %1}, [%2];"
                 : "=l"(r.x), "=l"(r.y) : "l"(p));
    return r;
}

// ================= single fused kernel =================
__global__ __launch_bounds__(NTHR, 1) void xlstm_kernel(
    float* __restrict__ out, const float* __restrict__ x,
    const float* __restrict__ Wi, const float* __restrict__ Wf,
    const float* __restrict__ Wo, const float* __restrict__ Wc,
    const float* __restrict__ We,
    const float* __restrict__ bi, const float* __restrict__ bf,
    const float* __restrict__ bo, const float* __restrict__ bc,
    const float* __restrict__ be,
    const float* __restrict__ Ui, const float* __restrict__ Uf,
    const float* __restrict__ Uo, const float* __restrict__ Uc,
    const float* __restrict__ Ue)
{
    extern __shared__ float sm[];
    float* Ud  = sm + OFF_UD;
    float* cr  = sm + OFF_CR;
    float* ps2 = sm + OFF_PS2;
    float* zt  = sm + OFF_ZT;
    float* zes = sm + OFF_ZES;
    float* hst = sm + OFF_HST;
    float* psb = sm + OFF_PSB;
    unsigned int* gf = (unsigned int*)(sm + OFF_GF);
    __shared__ unsigned sR;

    const int bid = blockIdx.x;
    const int tid = threadIdx.x;
    const bool isE = (bid >= NUBLK);

    if (tid == 0) {
        unsigned old = atomicAdd(&g_tix.v, 1u);
        sR = old / (unsigned)NBLK;
    }
    if (tid < 16) gf[tid] = 0u;
    __syncthreads();
    const unsigned R = sR;
    const unsigned HB = R * 65536u;       // h counter base (128*512)
    const unsigned EB = R * 4096u;        // e counter base (8*512)

    // ======== gate warp (tids 512..543): single-lane counter polls ========
    if (tid >= 512) {
        const int lane = tid - 512;
        if (lane == 0) {
            for (int s2 = 1; s2 < Tt; s2++) {
                while (ld_acq(&g_hcnt.v) < HB + 128u * (unsigned)s2) { }
                st_rel_sh(&gf[0], (unsigned)s2);
            }
        } else if (lane == 1 && !isE) {
            for (int t = 0; t < Tt; t++) {
                while (ld_acq(&g_ecnt.v) < EB + 8u * (unsigned)(t + 1)) { }
                st_rel_sh(&gf[1], (unsigned)(t + 1));
            }
        }
        return;
    }

    // ================= PHASE A: precompute Z =================
    {
        const int team = tid >> 8;
        const int ttid = tid & 255;
        float* xs = sm + (team ? OFF_XS1 : OFF_XS0);
        float* Ws = sm + (team ? OFF_WS1 : OFF_WS0);
        const int barid = 2 + team;
        const int ptx = ttid & 15, pty = ttid >> 4;

        for (int tile = bid * 2 + team; tile < NTILES; tile += NBLK * 2) {
            const int t  = tile / 33;
            const int nt = tile % 33;
            const float* W; const float* bv;
            switch (nt >> 3) {
                case 0:  W = Wi; bv = bi; break;
                case 1:  W = Wf; bv = bf; break;
                case 2:  W = Wo; bv = bo; break;
                case 3:  W = Wc; bv = bc; break;
                default: W = We; bv = be; break;
            }
            const int stride = (nt < 32) ? Uu : Mm;
            const int col0   = (nt & 7) * 64;

            unsigned long long acc01[4], acc23[4];
            {
                unsigned long long p01 = pack2(bv[col0 + ptx * 4 + 0], bv[col0 + ptx * 4 + 1]);
                unsigned long long p23 = pack2(bv[col0 + ptx * 4 + 2], bv[col0 + ptx * 4 + 3]);
                #pragma unroll
                for (int i = 0; i < 4; i++) { acc01[i] = p01; acc23[i] = p23; }
            }
            for (int kb = 0; kb < 4; kb++) {
                TBAR(barid);
                #pragma unroll
                for (int l = 0; l < 16; l++) {
                    int idx = l * 256 + ttid;
                    int b = idx >> 6, kk = idx & 63;
                    xs[b * 65 + kk] = x[(size_t)b * Tt * Dd + (size_t)t * Dd + kb * 64 + kk];
                }
                #pragma unroll
                for (int l = 0; l < 16; l++) {
                    int idx = l * 256 + ttid;
                    int kk = idx >> 6, nn = idx & 63;
                    Ws[kk * 64 + nn] = W[(size_t)(kb * 64 + kk) * stride + col0 + nn];
                }
                TBAR(barid);
                #pragma unroll 16
                for (int kk = 0; kk < 64; kk++) {
                    ulonglong2 wv = *reinterpret_cast<const ulonglong2*>(&Ws[kk * 64 + ptx * 4]);
                    #pragma unroll
                    for (int i = 0; i < 4; i++) {
                        float xv = xs[(pty * 4 + i) * 65 + kk];
                        unsigned long long xx = pack2(xv, xv);
                        fma2(acc01[i], xx, wv.x);
                        fma2(acc23[i], xx, wv.y);
                    }
                }
            }
            float a[4][4];
            #pragma unroll
            for (int i = 0; i < 4; i++) {
                unpack2(acc01[i], a[i][0], a[i][1]);
                unpack2(acc23[i], a[i][2], a[i][3]);
            }
            #pragma unroll
            for (int j = 0; j < 4; j++) {
                int n = nt * 64 + ptx * 4 + j;
                float4 v = make_float4(a[0][j], a[1][j], a[2][j], a[3][j]);
                *reinterpret_cast<float4*>(&g_Z[((size_t)t * NZt + n) * Bb + pty * 4]) = v;
            }
        }
    }
    NBAR();
    if (tid == 0) {
        MEMBAR_GL();
        red_rel(&g_zdone.v);
        while (ld_acq(&g_zdone.v) < (R + 1u) * (unsigned)NBLK) { }
    }
    NBAR();

    // ================= load duplicated U slice (once) =================
    const int u0 = bid * 4;
    const int m0 = (bid - NUBLK) * 8;
    {
        const int c = tid & 15, kk0 = tid >> 4;
        if (!isE) {
            const float* Ug;
            switch (c >> 2) {
                case 0:  Ug = Ui; break;
                case 1:  Ug = Uf; break;
                case 2:  Ug = Uo; break;
                default: Ug = Uc; break;
            }
            const int lc = u0 + (c & 3);
            for (int k = kk0; k < Uu; k += 32) {
                float v = Ug[(size_t)k * Uu + lc];
                Ud[k * 32 + c * 2] = v;
                Ud[k * 32 + c * 2 + 1] = v;
            }
        } else {
            for (int k = kk0; k < Uu; k += 32) {
                float v = (c < 8) ? Ue[(size_t)k * Mm + m0 + c] : 0.f;
                Ud[k * 32 + c * 2] = v;
                Ud[k * 32 + c * 2 + 1] = v;
            }
        }
    }
    NBAR();

    // ================= PHASE B: recurrence =================
    const int s    = tid >> 5;                    // warp = split-K slice
    const int lidw = tid & 31;
    const int bgrp = lidw & 7, cgrp = lidw >> 3;
    const int kbase = s * 32;
    const int rc = tid >> 5, rb = tid & 31;
    const int p2h = tid >> 8;
    const int item = tid & 255;

    int zcol; bool zvalid;
    if (!isE) { zcol = (rc >> 2) * Uu + u0 + (rc & 3); zvalid = true; }
    else      { zvalid = (rc < 8); zcol = 4 * Uu + m0 + (zvalid ? rc : 0); }

    for (int t = 0; t < Tt; t++) {
        float z0 = 0.f, z1 = 0.f;
        if (zvalid) {
            const float* zp = &g_Z[((size_t)t * NZt + zcol) * Bb];
            z0 = __ldcs(zp + rb);
            z1 = __ldcs(zp + 32 + rb);
        }

        if (t > 0) {
            if (tid == 0) { while (ld_acq_sh(&gf[0]) < (unsigned)t) { } }
            NBAR();

            // ---- GEMM: h direct from L2 (__ldcg), single pass over 64 b ----
            unsigned long long acc[2][2][4];
            #pragma unroll
            for (int a = 0; a < 2; a++)
                #pragma unroll
                for (int b2 = 0; b2 < 2; b2++)
                    #pragma unroll
                    for (int j = 0; j < 4; j++) acc[a][b2][j] = 0ull;

            const char* hbase = (const char*)(&g_hTT[t & 1][0][0] + kbase * 64 + bgrp * 4);
            const float* up = &Ud[kbase * 32 + cgrp * 8];
            #pragma unroll 8
            for (int k = 0; k < 32; k++) {
                ulonglong2 h0 = ldcg2(hbase + k * 256);          // b quad, half 0
                ulonglong2 h1 = ldcg2(hbase + k * 256 + 128);    // b quad, half 1
                ulonglong2 u01 = *reinterpret_cast<const ulonglong2*>(up + k * 32);
                ulonglong2 u23 = *reinterpret_cast<const ulonglong2*>(up + k * 32 + 4);
                fma2(acc[0][0][0], h0.x, u01.x);
                fma2(acc[0][0][1], h0.x, u01.y);
                fma2(acc[0][0][2], h0.x, u23.x);
                fma2(acc[0][0][3], h0.x, u23.y);
                fma2(acc[0][1][0], h0.y, u01.x);
                fma2(acc[0][1][1], h0.y, u01.y);
                fma2(acc[0][1][2], h0.y, u23.x);
                fma2(acc[0][1][3], h0.y, u23.y);
                fma2(acc[1][0][0], h1.x, u01.x);
                fma2(acc[1][0][1], h1.x, u01.y);
                fma2(acc[1][0][2], h1.x, u23.x);
                fma2(acc[1][0][3], h1.x, u23.y);
                fma2(acc[1][1][0], h1.y, u01.x);
                fma2(acc[1][1][1], h1.y, u01.y);
                fma2(acc[1][1][2], h1.y, u23.x);
                fma2(acc[1][1][3], h1.y, u23.y);
            }

            // ---- stage split-K partials (ps2 dedicated: no alias barrier) ----
            #pragma unroll
            for (int hh = 0; hh < 2; hh++)
                #pragma unroll
                for (int j = 0; j < 4; j++) {
                    const int base = (s * 16 + cgrp * 4 + j) * 68 + hh * 32 + bgrp * 4;
                    *reinterpret_cast<unsigned long long*>(&ps2[base])     = acc[hh][0][j];
                    *reinterpret_cast<unsigned long long*>(&ps2[base + 2]) = acc[hh][1][j];
                }
            NBAR();

            // ---- reduce 16 slices + Z ----
            {
                float v0 = 0.f, v1 = 0.f;
                #pragma unroll
                for (int s2 = 0; s2 < 16; s2++) {
                    v0 += ps2[(s2 * 16 + rc) * 68 + rb];
                    v1 += ps2[(s2 * 16 + rc) * 68 + 32 + rb];
                }
                if (!isE) {
                    zt[rc * 65 + rb]      = v0 + z0;
                    zt[rc * 65 + 32 + rb] = v1 + z1;
                } else if (zvalid) {
                    g_ze[rb][m0 + rc]      = v0 + z0;
                    g_ze[32 + rb][m0 + rc] = v1 + z1;
                }
            }
            NBAR();
        } else {
            if (!isE) {
                zt[rc * 65 + rb]      = z0;
                zt[rc * 65 + 32 + rb] = z1;
            } else if (zvalid) {
                g_ze[rb][m0 + rc]      = z0;
                g_ze[32 + rb][m0 + rc] = z1;
            }
            NBAR();
        }

        if (isE) {
            if (tid == 0) { MEMBAR_GL(); red_rel(&g_ecnt.v); }
            continue;
        }

        // ---- u-blocks: activations early (registers), overlapped with e wait ----
        float iv = 0.f, fv = 0.f, ov = 0.f, cv = 0.f;
        if (tid < 256) {
            const int uul = tid >> 6, b = tid & 63;
            float zi = zt[(uul)      * 65 + b];
            float zf = zt[(4 + uul)  * 65 + b];
            float zo = zt[(8 + uul)  * 65 + b];
            float zc = zt[(12 + uul) * 65 + b];
            iv = __fdividef(1.f, 1.f + __expf(-zi));
            fv = __fdividef(1.f, 1.f + __expf(-zf));
            ov = __fdividef(1.f, 1.f + __expf(-zo));
            float t2 = __expf(2.f * zc);
            cv = __fdividef(t2 - 1.f, t2 + 1.f);
        }
        if (tid == 0) { while (ld_acq_sh(&gf[1]) < (unsigned)(t + 1)) { } }
        NBAR();

        // ---- local softmax: 8 lanes per batch row, direct from L2 ----
        {
            const int sb = tid >> 3, sq = tid & 7;
            const float4* zrow = reinterpret_cast<const float4*>(&g_ze[sb][sq * 8]);
            float4 v0 = __ldcg(zrow);
            float4 v1 = __ldcg(zrow + 1);
            float v[8] = {v0.x, v0.y, v0.z, v0.w, v1.x, v1.y, v1.z, v1.w};
            float mx = -1e30f;
            #pragma unroll
            for (int i = 0; i < 8; i++) mx = fmaxf(mx, v[i]);
            mx = fmaxf(mx, __shfl_xor_sync(0xffffffffu, mx, 1));
            mx = fmaxf(mx, __shfl_xor_sync(0xffffffffu, mx, 2));
            mx = fmaxf(mx, __shfl_xor_sync(0xffffffffu, mx, 4));
            float sum = 0.f;
            #pragma unroll
            for (int i = 0; i < 8; i++) { v[i] = __expf(v[i] - mx); sum += v[i]; }
            sum += __shfl_xor_sync(0xffffffffu, sum, 1);
            sum += __shfl_xor_sync(0xffffffffu, sum, 2);
            sum += __shfl_xor_sync(0xffffffffu, sum, 4);
            float inv = __fdividef(1.f, sum);
            #pragma unroll
            for (int i = 0; i < 8; i++) zes[sb * 65 + sq * 8 + i] = v[i] * inv;
        }
        NBAR();

        // ---- phase 2: memory read from SMEM c-ring (m split across halves) ----
        {
            const int uul = item >> 6, b = item & 63;
            const int lo = p2h * 32;
            float p = 0.f;
            const float* zr = &zes[b * 65];
            if (t >= 64) {
                #pragma unroll
                for (int mm = 0; mm < 32; mm++) {
                    int m = lo + mm;
                    p += zr[m] * cr[(((t - 1 - m) & 63) * 4 + uul) * 64 + b];
                }
            } else {
                const int hi = (t < lo + 32) ? t : lo + 32;
                for (int m = lo; m < hi; m++)
                    p += zr[m] * cr[(((t - 1 - m) & 63) * 4 + uul) * 64 + b];
            }
            if (p2h == 1) psb[item] = p;
            NBAR();
            if (p2h == 0) {
                float mc = p + psb[item];
                float c = fv * mc + iv * cv;
                float t2c = __expf(2.f * c);
                float th = __fdividef(t2c - 1.f, t2c + 1.f);
                float h = ov * th;
                cr[((t & 63) * 4 + uul) * 64 + b] = c;
                hst[uul * 64 + b] = h;
            }
        }
        NBAR();
        // ---- stores: out (by b) + transposed h (by u row) ----
        if (tid < 64) {
            const int b = tid;
            float4 hv = make_float4(hst[b], hst[64 + b], hst[128 + b], hst[192 + b]);
            *reinterpret_cast<float4*>(&out[((size_t)b * Tt + t) * Uu + u0]) = hv;
        } else if (tid < 128) {
            const int r = tid - 64, uul = r >> 4, seg = r & 15;
            float4 hv = *reinterpret_cast<const float4*>(&hst[uul * 64 + seg * 4]);
            *reinterpret_cast<float4*>(&g_hTT[(t + 1) & 1][u0 + uul][seg * 4]) = hv;
        }
        NBAR();
        if (tid == 0) { MEMBAR_GL(); red_rel(&g_hcnt.v); }
    }
}

// ---------------- launch: ONE kernel ----------------
extern "C" void kernel_launch(void* const* d_in, const int* in_sizes, int n_in,
                              void* d_out, int out_size) {
    (void)in_sizes; (void)n_in; (void)out_size;
    const float* x  = (const float*)d_in[0];
    const float* Wi = (const float*)d_in[1];
    const float* Ui = (const float*)d_in[2];
    const float* bi = (const float*)d_in[3];
    const float* Wf = (const float*)d_in[4];
    const float* Uf = (const float*)d_in[5];
    const float* bf = (const float*)d_in[6];
    const float* Wo = (const float*)d_in[7];
    const float* Uo = (const float*)d_in[8];
    const float* bo = (const float*)d_in[9];
    const float* Wc = (const float*)d_in[10];
    const float* Uc = (const float*)d_in[11];
    const float* bc = (const float*)d_in[12];
    const float* We = (const float*)d_in[13];
    const float* Ue = (const float*)d_in[14];
    const float* be = (const float*)d_in[15];
    float* out = (float*)d_out;

    const size_t SMEM = (size_t)SMEM_F * sizeof(float);   // 223616 B
    cudaFuncSetAttribute(xlstm_kernel, cudaFuncAttributeMaxDynamicSharedMemorySize, (int)SMEM);

    xlstm_kernel<<<NBLK, NTHR, SMEM>>>(out, x,
        Wi, Wf, Wo, Wc, We, bi, bf, bo, bc, be,
        Ui, Uf, Uo, Uc, Ue);
}

// round 16
// speedup vs baseline: 3.3544x; 1.1583x over previous
#include <cuda_runtime.h>
#include <math.h>
#include <stdint.h>

// Problem constants
#define Tt   512
#define Bb   64
#define Dd   256
#define Uu   512
#define Mm   64
#define NZt  2112   // 4*U + M

#define NUBLK 128   // u-blocks: 4 u-cols each (16 z-cols)
#define NEBLK 8     // e-blocks: 8 e-cols each
#define NBLK  136
#define NTHR  544   // 512 main threads + 1 gate warp
#define NTILES (33 * 512)

// ---------------- device scratch (free-running across graph replays) ----------------
__device__ float g_Z[(size_t)Tt * NZt * Bb];   // Z[t][n][b]
__device__ float g_hTT[2][Uu][Bb];             // hidden state TRANSPOSED [u][b], double buffered
__device__ float g_ze[Bb][Mm];                 // pre-softmax e logits

struct __align__(128) Cnt { unsigned int v; unsigned int pad[31]; };
__device__ Cnt g_hcnt8[8];    // striped h arrivals (16 per stripe per step)
__device__ Cnt g_ecnt;        // ze arrivals (8/step)
__device__ Cnt g_zdone;       // Z-phase barrier (+136 per replay)
__device__ Cnt g_tix;         // replay ticket counter (+136 per replay)

// SMEM float offsets
#define OFF_UD   0            // U duplicated [512 k][32] = 16384
#define OFF_CR   16384        // cring [64 slot][4 u][64 b] = 16384 (SMEM)
#define OFF_PS2  32768        // split-K partials [256 rows][68] = 17408
#define OFF_ZT   50176        // zt [16 c][65] = 1040
#define OFF_ZES  51216        // probs [64 b][65] = 4160
#define OFF_HST  55376        // h staging [4 uul][64 b] = 256
#define OFF_GF   55632        // flags: 0=h ready t, 1=ze ready t+1
#define SMEM_F   55648        // 222592 bytes
// Z-phase scratch (overlaps UD/CR head, used strictly before recurrence)
#define OFF_XS0  0
#define OFF_WS0  4160
#define OFF_XS1  8256
#define OFF_WS1  12416

// ---------------- PTX helpers ----------------
__device__ __forceinline__ unsigned ld_acq(const unsigned int* p) {
    unsigned v;
    asm volatile("ld.acquire.gpu.global.u32 %0, [%1];" : "=r"(v) : "l"(p));
    return v;
}
__device__ __forceinline__ void red_rel(unsigned int* p) {
    asm volatile("red.release.gpu.global.add.u32 [%0], 1;" :: "l"(p));
}
__device__ __forceinline__ unsigned ld_acq_sh(const unsigned int* p) {
    unsigned v, a = (unsigned)__cvta_generic_to_shared(p);
    asm volatile("ld.acquire.cta.shared.u32 %0, [%1];" : "=r"(v) : "r"(a));
    return v;
}
__device__ __forceinline__ void st_rel_sh(unsigned int* p, unsigned v) {
    unsigned a = (unsigned)__cvta_generic_to_shared(p);
    asm volatile("st.release.cta.shared.u32 [%0], %1;" :: "r"(a), "r"(v));
}
#define MEMBAR_GL() asm volatile("membar.gl;" ::: "memory")
#define NBAR() asm volatile("bar.sync 1, 512;" ::: "memory")
#define TBAR(id) asm volatile("bar.sync %0, 256;" :: "r"(id) : "memory")

// packed fp32x2 FMA (FFMA2)
__device__ __forceinline__ unsigned long long pack2(float a, float b) {
    unsigned long long r;
    asm("mov.b64 %0, {%1, %2};" : "=l"(r) : "f"(a), "f"(b));
    return r;
}
__device__ __forceinline__ void fma2(unsigned long long& d,
                                     unsigned long long a, unsigned long long b) {
    asm("fma.rn.f32x2 %0, %1, %2, %0;" : "+l"(d) : "l"(a), "l"(b));
}
__device__ __forceinline__ void unpack2(unsigned long long v, float& a, float& b) {
    asm("mov.b64 {%0, %1}, %2;" : "=f"(a), "=f"(b) : "l"(v));
}
// 16B L2-only load (bypasses L1: h is cross-SM mutable)
__device__ __forceinline__ ulonglong2 ldcg2(const void* p) {
    ulonglong2 r;
    asm volatile("ld.global.cg.v2.u64 {%0, %1}, [%2];"
                 : "=l"(r.x), "=l"(r.y) : "l"(p));
    return r;
}

// ================= single fused kernel =================
__global__ __launch_bounds__(NTHR, 1) void xlstm_kernel(
    float* __restrict__ out, const float* __restrict__ x,
    const float* __restrict__ Wi, const float* __restrict__ Wf,
    const float* __restrict__ Wo, const float* __restrict__ Wc,
    const float* __restrict__ We,
    const float* __restrict__ bi, const float* __restrict__ bf,
    const float* __restrict__ bo, const float* __restrict__ bc,
    const float* __restrict__ be,
    const float* __restrict__ Ui, const float* __restrict__ Uf,
    const float* __restrict__ Uo, const float* __restrict__ Uc,
    const float* __restrict__ Ue)
{
    extern __shared__ float sm[];
    float* Ud  = sm + OFF_UD;
    float* cr  = sm + OFF_CR;
    float* ps2 = sm + OFF_PS2;
    float* zt  = sm + OFF_ZT;
    float* zes = sm + OFF_ZES;
    float* hst = sm + OFF_HST;
    unsigned int* gf = (unsigned int*)(sm + OFF_GF);
    __shared__ unsigned sR;

    const int bid = blockIdx.x;
    const int tid = threadIdx.x;
    const bool isE = (bid >= NUBLK);

    if (tid == 0) {
        unsigned old = atomicAdd(&g_tix.v, 1u);
        sR = old / (unsigned)NBLK;
    }
    if (tid < 16) gf[tid] = 0u;
    __syncthreads();
    const unsigned R = sR;
    const unsigned HB8 = R * 8192u;       // per-stripe base (16*512)
    const unsigned EB  = R * 4096u;       // e counter base (8*512)

    // ======== gate warp (tids 512..543): striped counter polls ========
    if (tid >= 512) {
        const int lane = tid - 512;
        if (lane < 8) {
            // lanes 0-7: each watches one h stripe; vote; lane 0 publishes
            for (int s2 = 1; s2 < Tt; s2++) {
                const unsigned tgt = HB8 + 16u * (unsigned)s2;
                bool ok;
                do {
                    ok = (ld_acq(&g_hcnt8[lane].v) >= tgt);
                } while (!__all_sync(0x000000FFu, ok));
                if (lane == 0) st_rel_sh(&gf[0], (unsigned)s2);
            }
        } else if (lane == 8 && !isE) {
            for (int t = 0; t < Tt; t++) {
                while (ld_acq(&g_ecnt.v) < EB + 8u * (unsigned)(t + 1)) { }
                st_rel_sh(&gf[1], (unsigned)(t + 1));
            }
        }
        return;
    }

    // ================= PHASE A: precompute Z =================
    {
        const int team = tid >> 8;
        const int ttid = tid & 255;
        float* xs = sm + (team ? OFF_XS1 : OFF_XS0);
        float* Ws = sm + (team ? OFF_WS1 : OFF_WS0);
        const int barid = 2 + team;
        const int ptx = ttid & 15, pty = ttid >> 4;

        for (int tile = bid * 2 + team; tile < NTILES; tile += NBLK * 2) {
            const int t  = tile / 33;
            const int nt = tile % 33;
            const float* W; const float* bv;
            switch (nt >> 3) {
                case 0:  W = Wi; bv = bi; break;
                case 1:  W = Wf; bv = bf; break;
                case 2:  W = Wo; bv = bo; break;
                case 3:  W = Wc; bv = bc; break;
                default: W = We; bv = be; break;
            }
            const int stride = (nt < 32) ? Uu : Mm;
            const int col0   = (nt & 7) * 64;

            unsigned long long acc01[4], acc23[4];
            {
                unsigned long long p01 = pack2(bv[col0 + ptx * 4 + 0], bv[col0 + ptx * 4 + 1]);
                unsigned long long p23 = pack2(bv[col0 + ptx * 4 + 2], bv[col0 + ptx * 4 + 3]);
                #pragma unroll
                for (int i = 0; i < 4; i++) { acc01[i] = p01; acc23[i] = p23; }
            }
            for (int kb = 0; kb < 4; kb++) {
                TBAR(barid);
                #pragma unroll
                for (int l = 0; l < 16; l++) {
                    int idx = l * 256 + ttid;
                    int b = idx >> 6, kk = idx & 63;
                    xs[b * 65 + kk] = x[(size_t)b * Tt * Dd + (size_t)t * Dd + kb * 64 + kk];
                }
                #pragma unroll
                for (int l = 0; l < 16; l++) {
                    int idx = l * 256 + ttid;
                    int kk = idx >> 6, nn = idx & 63;
                    Ws[kk * 64 + nn] = W[(size_t)(kb * 64 + kk) * stride + col0 + nn];
                }
                TBAR(barid);
                #pragma unroll 16
                for (int kk = 0; kk < 64; kk++) {
                    ulonglong2 wv = *reinterpret_cast<const ulonglong2*>(&Ws[kk * 64 + ptx * 4]);
                    #pragma unroll
                    for (int i = 0; i < 4; i++) {
                        float xv = xs[(pty * 4 + i) * 65 + kk];
                        unsigned long long xx = pack2(xv, xv);
                        fma2(acc01[i], xx, wv.x);
                        fma2(acc23[i], xx, wv.y);
                    }
                }
            }
            float a[4][4];
            #pragma unroll
            for (int i = 0; i < 4; i++) {
                unpack2(acc01[i], a[i][0], a[i][1]);
                unpack2(acc23[i], a[i][2], a[i][3]);
            }
            #pragma unroll
            for (int j = 0; j < 4; j++) {
                int n = nt * 64 + ptx * 4 + j;
                float4 v = make_float4(a[0][j], a[1][j], a[2][j], a[3][j]);
                *reinterpret_cast<float4*>(&g_Z[((size_t)t * NZt + n) * Bb + pty * 4]) = v;
            }
        }
    }
    NBAR();
    if (tid == 0) {
        MEMBAR_GL();
        red_rel(&g_zdone.v);
        while (ld_acq(&g_zdone.v) < (R + 1u) * (unsigned)NBLK) { }
    }
    NBAR();

    // ================= load duplicated U slice (once) =================
    const int u0 = bid * 4;
    const int m0 = (bid - NUBLK) * 8;
    {
        const int c = tid & 15, kk0 = tid >> 4;
        if (!isE) {
            const float* Ug;
            switch (c >> 2) {
                case 0:  Ug = Ui; break;
                case 1:  Ug = Uf; break;
                case 2:  Ug = Uo; break;
                default: Ug = Uc; break;
            }
            const int lc = u0 + (c & 3);
            for (int k = kk0; k < Uu; k += 32) {
                float v = Ug[(size_t)k * Uu + lc];
                Ud[k * 32 + c * 2] = v;
                Ud[k * 32 + c * 2 + 1] = v;
            }
        } else {
            for (int k = kk0; k < Uu; k += 32) {
                float v = (c < 8) ? Ue[(size_t)k * Mm + m0 + c] : 0.f;
                Ud[k * 32 + c * 2] = v;
                Ud[k * 32 + c * 2 + 1] = v;
            }
        }
    }
    NBAR();

    // ================= PHASE B: recurrence =================
    const int s    = tid >> 5;                    // warp = split-K slice
    const int lidw = tid & 31;
    const int bgrp = lidw & 7, cgrp = lidw >> 3;
    const int kbase = s * 32;
    const int rc = tid >> 5, rb = tid & 31;

    int zcol; bool zvalid;
    if (!isE) { zcol = (rc >> 2) * Uu + u0 + (rc & 3); zvalid = true; }
    else      { zvalid = (rc < 8); zcol = 4 * Uu + m0 + (zvalid ? rc : 0); }

    for (int t = 0; t < Tt; t++) {
        float z0 = 0.f, z1 = 0.f;
        if (zvalid) {
            const float* zp = &g_Z[((size_t)t * NZt + zcol) * Bb];
            z0 = __ldcs(zp + rb);
            z1 = __ldcs(zp + 32 + rb);
        }

        if (t > 0) {
            // ---- h gate: all threads spin on SMEM flag (no barrier) ----
            while (ld_acq_sh(&gf[0]) < (unsigned)t) { }

            // ---- GEMM: h direct from L2 (__ldcg), single pass over 64 b ----
            unsigned long long acc[2][2][4];
            #pragma unroll
            for (int a = 0; a < 2; a++)
                #pragma unroll
                for (int b2 = 0; b2 < 2; b2++)
                    #pragma unroll
                    for (int j = 0; j < 4; j++) acc[a][b2][j] = 0ull;

            const char* hbase = (const char*)(&g_hTT[t & 1][0][0] + kbase * 64 + bgrp * 4);
            const float* up = &Ud[kbase * 32 + cgrp * 8];
            #pragma unroll 8
            for (int k = 0; k < 32; k++) {
                ulonglong2 h0 = ldcg2(hbase + k * 256);          // b quad, half 0
                ulonglong2 h1 = ldcg2(hbase + k * 256 + 128);    // b quad, half 1
                ulonglong2 u01 = *reinterpret_cast<const ulonglong2*>(up + k * 32);
                ulonglong2 u23 = *reinterpret_cast<const ulonglong2*>(up + k * 32 + 4);
                fma2(acc[0][0][0], h0.x, u01.x);
                fma2(acc[0][0][1], h0.x, u01.y);
                fma2(acc[0][0][2], h0.x, u23.x);
                fma2(acc[0][0][3], h0.x, u23.y);
                fma2(acc[0][1][0], h0.y, u01.x);
                fma2(acc[0][1][1], h0.y, u01.y);
                fma2(acc[0][1][2], h0.y, u23.x);
                fma2(acc[0][1][3], h0.y, u23.y);
                fma2(acc[1][0][0], h1.x, u01.x);
                fma2(acc[1][0][1], h1.x, u01.y);
                fma2(acc[1][0][2], h1.x, u23.x);
                fma2(acc[1][0][3], h1.x, u23.y);
                fma2(acc[1][1][0], h1.y, u01.x);
                fma2(acc[1][1][1], h1.y, u01.y);
                fma2(acc[1][1][2], h1.y, u23.x);
                fma2(acc[1][1][3], h1.y, u23.y);
            }

            // ---- stage split-K partials ----
            #pragma unroll
            for (int hh = 0; hh < 2; hh++)
                #pragma unroll
                for (int j = 0; j < 4; j++) {
                    const int base = (s * 16 + cgrp * 4 + j) * 68 + hh * 32 + bgrp * 4;
                    *reinterpret_cast<unsigned long long*>(&ps2[base])     = acc[hh][0][j];
                    *reinterpret_cast<unsigned long long*>(&ps2[base + 2]) = acc[hh][1][j];
                }
            NBAR();

            // ---- reduce 16 slices + Z ----
            {
                float v0 = 0.f, v1 = 0.f;
                #pragma unroll
                for (int s2 = 0; s2 < 16; s2++) {
                    v0 += ps2[(s2 * 16 + rc) * 68 + rb];
                    v1 += ps2[(s2 * 16 + rc) * 68 + 32 + rb];
                }
                if (!isE) {
                    zt[rc * 65 + rb]      = v0 + z0;
                    zt[rc * 65 + 32 + rb] = v1 + z1;
                } else if (zvalid) {
                    g_ze[rb][m0 + rc]      = v0 + z0;
                    g_ze[32 + rb][m0 + rc] = v1 + z1;
                }
            }
            NBAR();
        } else {
            if (!isE) {
                zt[rc * 65 + rb]      = z0;
                zt[rc * 65 + 32 + rb] = z1;
            } else if (zvalid) {
                g_ze[rb][m0 + rc]      = z0;
                g_ze[32 + rb][m0 + rc] = z1;
            }
            NBAR();
        }

        if (isE) {
            if (tid == 0) { MEMBAR_GL(); red_rel(&g_ecnt.v); }
            continue;
        }

        // ---- u-blocks: activations early (registers), overlap the e wait ----
        float iv = 0.f, fv = 0.f, ov = 0.f, cv = 0.f;
        if (tid < 256) {
            const int uul = tid >> 6, b = tid & 63;
            float zi = zt[(uul)      * 65 + b];
            float zf = zt[(4 + uul)  * 65 + b];
            float zo = zt[(8 + uul)  * 65 + b];
            float zc = zt[(12 + uul) * 65 + b];
            iv = __fdividef(1.f, 1.f + __expf(-zi));
            fv = __fdividef(1.f, 1.f + __expf(-zf));
            ov = __fdividef(1.f, 1.f + __expf(-zo));
            float t2 = __expf(2.f * zc);
            cv = __fdividef(t2 - 1.f, t2 + 1.f);
        }
        // ---- e gate: all threads spin on SMEM flag (no barrier) ----
        while (ld_acq_sh(&gf[1]) < (unsigned)(t + 1)) { }

        // ---- local softmax: 8 lanes per batch row, direct from L2 ----
        {
            const int sb = tid >> 3, sq = tid & 7;
            const float4* zrow = reinterpret_cast<const float4*>(&g_ze[sb][sq * 8]);
            float4 v0 = __ldcg(zrow);
            float4 v1 = __ldcg(zrow + 1);
            float v[8] = {v0.x, v0.y, v0.z, v0.w, v1.x, v1.y, v1.z, v1.w};
            float mx = -1e30f;
            #pragma unroll
            for (int i = 0; i < 8; i++) mx = fmaxf(mx, v[i]);
            mx = fmaxf(mx, __shfl_xor_sync(0xffffffffu, mx, 1));
            mx = fmaxf(mx, __shfl_xor_sync(0xffffffffu, mx, 2));
            mx = fmaxf(mx, __shfl_xor_sync(0xffffffffu, mx, 4));
            float sum = 0.f;
            #pragma unroll
            for (int i = 0; i < 8; i++) { v[i] = __expf(v[i] - mx); sum += v[i]; }
            sum += __shfl_xor_sync(0xffffffffu, sum, 1);
            sum += __shfl_xor_sync(0xffffffffu, sum, 2);
            sum += __shfl_xor_sync(0xffffffffu, sum, 4);
            float inv = __fdividef(1.f, sum);
            #pragma unroll
            for (int i = 0; i < 8; i++) zes[sb * 65 + sq * 8 + i] = v[i] * inv;
        }
        NBAR();

        // ---- phase 2: memory read from SMEM c-ring (single pass, 64 m) ----
        if (tid < 256) {
            const int uul = tid >> 6, b = tid & 63;
            float p = 0.f;
            const float* zr = &zes[b * 65];
            if (t >= 64) {
                #pragma unroll
                for (int m = 0; m < 64; m++)
                    p += zr[m] * cr[(((t - 1 - m) & 63) * 4 + uul) * 64 + b];
            } else {
                for (int m = 0; m < t; m++)
                    p += zr[m] * cr[(((t - 1 - m) & 63) * 4 + uul) * 64 + b];
            }
            float c = fv * p + iv * cv;
            float t2c = __expf(2.f * c);
            float th = __fdividef(t2c - 1.f, t2c + 1.f);
            float h = ov * th;
            cr[((t & 63) * 4 + uul) * 64 + b] = c;
            hst[uul * 64 + b] = h;
        }
        NBAR();
        // ---- stores: out (by b) + transposed h (by u row) ----
        if (tid < 64) {
            const int b = tid;
            float4 hv = make_float4(hst[b], hst[64 + b], hst[128 + b], hst[192 + b]);
            *reinterpret_cast<float4*>(&out[((size_t)b * Tt + t) * Uu + u0]) = hv;
        } else if (tid < 128) {
            const int r = tid - 64, uul = r >> 4, seg = r & 15;
            float4 hv = *reinterpret_cast<const float4*>(&hst[uul * 64 + seg * 4]);
            *reinterpret_cast<float4*>(&g_hTT[(t + 1) & 1][u0 + uul][seg * 4]) = hv;
        }
        NBAR();
        if (tid == 0) { MEMBAR_GL(); red_rel(&g_hcnt8[bid & 7].v); }
    }
}

// ---------------- launch: ONE kernel ----------------
extern "C" void kernel_launch(void* const* d_in, const int* in_sizes, int n_in,
                              void* d_out, int out_size) {
    (void)in_sizes; (void)n_in; (void)out_size;
    const float* x  = (const float*)d_in[0];
    const float* Wi = (const float*)d_in[1];
    const float* Ui = (const float*)d_in[2];
    const float* bi = (const float*)d_in[3];
    const float* Wf = (const float*)d_in[4];
    const float* Uf = (const float*)d_in[5];
    const float* bf = (const float*)d_in[6];
    const float* Wo = (const float*)d_in[7];
    const float* Uo = (const float*)d_in[8];
    const float* bo = (const float*)d_in[9];
    const float* Wc = (const float*)d_in[10];
    const float* Uc = (const float*)d_in[11];
    const float* bc = (const float*)d_in[12];
    const float* We = (const float*)d_in[13];
    const float* Ue = (const float*)d_in[14];
    const float* be = (const float*)d_in[15];
    float* out = (float*)d_out;

    const size_t SMEM = (size_t)SMEM_F * sizeof(float);   // 222592 B
    cudaFuncSetAttribute(xlstm_kernel, cudaFuncAttributeMaxDynamicSharedMemorySize, (int)SMEM);

    xlstm_kernel<<<NBLK, NTHR, SMEM>>>(out, x,
        Wi, Wf, Wo, Wc, We, bi, bf, bo, bc, be,
        Ui, Uf, Uo, Uc, Ue);
}